// round 1
// baseline (speedup 1.0000x reference)
#include <cuda_runtime.h>
#include <math.h>

// ---------------------------------------------------------------------------
// Problem constants
// ---------------------------------------------------------------------------
static constexpr int B  = 16;
static constexpr int N  = 512;
static constexpr int D  = 512;
static constexpr int H  = 8;
static constexpr int HD = 64;     // head dim
static constexpr int LW = 64;
static constexpr int NQ = 10000;
static constexpr int BN_ROWS  = B * N;    // 8192
static constexpr int BLW_ROWS = B * LW;   // 1024

// ---------------------------------------------------------------------------
// Scratch (static device globals -- no allocation allowed)
// ---------------------------------------------------------------------------
__device__ float g_M     [BN_ROWS * D];
__device__ float g_E     [BN_ROWS * D];
__device__ float g_Q     [BN_ROWS * D];
__device__ float g_K     [BN_ROWS * D];
__device__ float g_V     [BN_ROWS * D];
__device__ float g_O     [BN_ROWS * D];
__device__ float g_Prob  [B * H * N * N];   // 64 MB scores/probs
__device__ float g_Sbase [BN_ROWS * D];
__device__ float g_Slocal[BN_ROWS * D];
__device__ float g_Sglob [BN_ROWS * D];
__device__ float g_Scross[BN_ROWS * D];
__device__ float g_Ssum  [BN_ROWS * D];
__device__ float g_T1    [BN_ROWS * D];
__device__ float g_T2    [BN_ROWS * D];

// ---------------------------------------------------------------------------
// Embedding gather: M = M_emb[q + NQ*r] + P[n],  E = E_emb[qry]
// ---------------------------------------------------------------------------
__global__ void embed_kernel(const int* __restrict__ q, const int* __restrict__ r,
                             const int* __restrict__ qry,
                             const float* __restrict__ M_emb,
                             const float* __restrict__ E_emb,
                             const float* __restrict__ P) {
    int row = blockIdx.x;                 // b*N + n
    int n = row & (N - 1);
    int x = q[row] + NQ * r[row];
    int e = qry[row];
    const float* msrc = M_emb + (size_t)x * D;
    const float* esrc = E_emb + (size_t)e * D;
    const float* psrc = P + (size_t)n * D;
    float* mdst = g_M + (size_t)row * D;
    float* edst = g_E + (size_t)row * D;
    for (int d = threadIdx.x; d < D; d += blockDim.x) {
        mdst[d] = msrc[d] + psrc[d];
        edst[d] = esrc[d];
    }
}

// ---------------------------------------------------------------------------
// Linear layer GEMM (NT): C[m,n] = sum_k A[m,k]*W[n,k] + bias[n] (+res) (relu)
// A: [M,K] rowmajor, W: [Nout,K] rowmajor. All dims multiples of 64, K=Nout=512.
// 64x64 tile, 256 threads, 4x4 per thread, BK=16.
// ---------------------------------------------------------------------------
__global__ void linear_kernel(const float* __restrict__ A, const float* __restrict__ W,
                              const float* __restrict__ bias, float* __restrict__ C,
                              int M, int Nout, int K,
                              const float* __restrict__ res1,
                              const float* __restrict__ res2, int relu) {
    constexpr int BK = 16;
    __shared__ float As[BK][64];
    __shared__ float Ws[BK][64];
    int m0 = blockIdx.y * 64;
    int n0 = blockIdx.x * 64;
    int tid = threadIdx.x;
    int tx = tid & 15, ty = tid >> 4;
    float acc[4][4] = {};
    for (int k0 = 0; k0 < K; k0 += BK) {
        for (int idx = tid; idx < 64 * BK; idx += 256) {
            int i = idx >> 4, j = idx & 15;
            As[j][i] = A[(size_t)(m0 + i) * K + k0 + j];
            Ws[j][i] = W[(size_t)(n0 + i) * K + k0 + j];
        }
        __syncthreads();
#pragma unroll
        for (int k = 0; k < BK; k++) {
            float a[4], w[4];
#pragma unroll
            for (int i = 0; i < 4; i++) a[i] = As[k][ty * 4 + i];
#pragma unroll
            for (int j = 0; j < 4; j++) w[j] = Ws[k][tx * 4 + j];
#pragma unroll
            for (int i = 0; i < 4; i++)
#pragma unroll
                for (int j = 0; j < 4; j++) acc[i][j] += a[i] * w[j];
        }
        __syncthreads();
    }
#pragma unroll
    for (int i = 0; i < 4; i++) {
        int m = m0 + ty * 4 + i;
#pragma unroll
        for (int j = 0; j < 4; j++) {
            int n = n0 + tx * 4 + j;
            size_t off = (size_t)m * Nout + n;
            float v = acc[i][j] + bias[n];
            if (res1) v += res1[off];
            if (res2) v += res2[off];
            if (relu) v = fmaxf(v, 0.f);
            C[off] = v;
        }
    }
}

// ---------------------------------------------------------------------------
// Attention scores: S[z,i,j] = dot(Q[b,i,h*64:], K[b,j,h*64:]) * 0.125
// z = b*H+h. grid (Nk/64, Nq/64, B*H). Causal tiles fully above diag skipped.
// ---------------------------------------------------------------------------
__global__ void attn_scores_kernel(const float* __restrict__ Q, const float* __restrict__ Kp,
                                   float* __restrict__ S, int Nq, int Nk, int causal) {
    int z = blockIdx.z, b = z / H, h = z - b * H;
    int i0 = blockIdx.y * 64, j0 = blockIdx.x * 64;
    if (causal && j0 > i0 + 63) return;
    const float* Qb = Q + (size_t)b * Nq * D + h * HD;
    const float* Kb = Kp + (size_t)b * Nk * D + h * HD;
    float* Sb = S + (size_t)z * Nq * Nk;
    __shared__ float Qs[16][64];
    __shared__ float Ks[16][64];
    int tid = threadIdx.x, tx = tid & 15, ty = tid >> 4;
    float acc[4][4] = {};
    for (int k0 = 0; k0 < HD; k0 += 16) {
        for (int idx = tid; idx < 64 * 16; idx += 256) {
            int i = idx >> 4, j = idx & 15;
            Qs[j][i] = Qb[(size_t)(i0 + i) * D + k0 + j];
            Ks[j][i] = Kb[(size_t)(j0 + i) * D + k0 + j];
        }
        __syncthreads();
#pragma unroll
        for (int k = 0; k < 16; k++) {
            float a[4], w[4];
#pragma unroll
            for (int i = 0; i < 4; i++) a[i] = Qs[k][ty * 4 + i];
#pragma unroll
            for (int j = 0; j < 4; j++) w[j] = Ks[k][tx * 4 + j];
#pragma unroll
            for (int i = 0; i < 4; i++)
#pragma unroll
                for (int j = 0; j < 4; j++) acc[i][j] += a[i] * w[j];
        }
        __syncthreads();
    }
#pragma unroll
    for (int i = 0; i < 4; i++) {
        int ii = i0 + ty * 4 + i;
#pragma unroll
        for (int j = 0; j < 4; j++)
            Sb[(size_t)ii * Nk + j0 + tx * 4 + j] = acc[i][j] * 0.125f;
    }
}

// ---------------------------------------------------------------------------
// Row softmax with optional causal mask; zero-fills masked tail.
// One block (128 thr) per row. rows = Z*Nq, row -> i = row % Nq.
// ---------------------------------------------------------------------------
__global__ void softmax_kernel(float* __restrict__ S, int Nq, int Nk, int causal) {
    int row = blockIdx.x;
    int i = row % Nq;
    float* Sr = S + (size_t)row * Nk;
    int lim = causal ? (i + 1) : Nk;
    int tid = threadIdx.x;
    __shared__ float red[128];
    float mx = -1e30f;
    for (int j = tid; j < lim; j += 128) mx = fmaxf(mx, Sr[j]);
    red[tid] = mx; __syncthreads();
    for (int s = 64; s > 0; s >>= 1) { if (tid < s) red[tid] = fmaxf(red[tid], red[tid + s]); __syncthreads(); }
    mx = red[0]; __syncthreads();
    float sum = 0.f;
    for (int j = tid; j < lim; j += 128) { float e = __expf(Sr[j] - mx); Sr[j] = e; sum += e; }
    red[tid] = sum; __syncthreads();
    for (int s = 64; s > 0; s >>= 1) { if (tid < s) red[tid] += red[tid + s]; __syncthreads(); }
    float inv = 1.f / red[0];
    for (int j = tid; j < lim; j += 128) Sr[j] *= inv;
    for (int j = lim + tid; j < Nk; j += 128) Sr[j] = 0.f;
}

// ---------------------------------------------------------------------------
// attn_w output: mean over heads of base probs -> d_out + B*N
// ---------------------------------------------------------------------------
__global__ void attn_mean_kernel(const float* __restrict__ Pm, float* __restrict__ out) {
    size_t idx = (size_t)blockIdx.x * blockDim.x + threadIdx.x;
    if (idx >= (size_t)B * N * N) return;
    size_t j = idx % N;
    size_t i = (idx / N) % N;
    size_t b = idx / ((size_t)N * N);
    float s = 0.f;
#pragma unroll
    for (int h = 0; h < H; h++)
        s += Pm[(((b * H + h) * N + i) * N) + j];
    out[idx] = s * (1.f / H);
}

// ---------------------------------------------------------------------------
// O = P @ V per (b,h): [Nq,Nk] x [Nk,64] -> O[b,i,h*64+e]. grid(1,Nq/64,B*H)
// ---------------------------------------------------------------------------
__global__ void attn_pv_kernel(const float* __restrict__ Pm, const float* __restrict__ V,
                               float* __restrict__ O, int Nq, int Nk, int causal) {
    int z = blockIdx.z, b = z / H, h = z - b * H;
    int i0 = blockIdx.y * 64;
    const float* Pb = Pm + (size_t)z * Nq * Nk;
    const float* Vb = V + (size_t)b * Nk * D + h * HD;
    float* Ob = O + (size_t)b * Nq * D + h * HD;
    __shared__ float Ps[64][17];
    __shared__ float Vs[16][64];
    int tid = threadIdx.x, tx = tid & 15, ty = tid >> 4;
    float acc[4][4] = {};
    int kend = causal ? min(Nk, i0 + 64) : Nk;
    for (int k0 = 0; k0 < kend; k0 += 16) {
        for (int idx = tid; idx < 64 * 16; idx += 256) {
            int i = idx >> 4, j = idx & 15;
            Ps[i][j] = Pb[(size_t)(i0 + i) * Nk + k0 + j];
        }
        for (int idx = tid; idx < 16 * 64; idx += 256) {
            int k = idx >> 6, e = idx & 63;
            Vs[k][e] = Vb[(size_t)(k0 + k) * D + e];
        }
        __syncthreads();
#pragma unroll
        for (int k = 0; k < 16; k++) {
            float a[4], w[4];
#pragma unroll
            for (int i = 0; i < 4; i++) a[i] = Ps[ty * 4 + i][k];
#pragma unroll
            for (int j = 0; j < 4; j++) w[j] = Vs[k][tx * 4 + j];
#pragma unroll
            for (int i = 0; i < 4; i++)
#pragma unroll
                for (int j = 0; j < 4; j++) acc[i][j] += a[i] * w[j];
        }
        __syncthreads();
    }
#pragma unroll
    for (int i = 0; i < 4; i++)
#pragma unroll
        for (int j = 0; j < 4; j++)
            Ob[(size_t)(i0 + ty * 4 + i) * D + tx * 4 + j] = acc[i][j];
}

// ---------------------------------------------------------------------------
// LayerNorm: out = LN(X + r1? + r2?) * g + b. One block (128 thr) per row.
// ---------------------------------------------------------------------------
__global__ void ln_kernel(const float* __restrict__ X, const float* __restrict__ r1,
                          const float* __restrict__ r2, const float* __restrict__ g,
                          const float* __restrict__ bvec, float* __restrict__ out) {
    int row = blockIdx.x;
    size_t base = (size_t)row * D;
    int tid = threadIdx.x;
    float v[4];
    float s = 0.f;
#pragma unroll
    for (int c = 0; c < 4; c++) {
        int d = tid + c * 128;
        float t = X[base + d];
        if (r1) t += r1[base + d];
        if (r2) t += r2[base + d];
        v[c] = t; s += t;
    }
    __shared__ float red[128];
    red[tid] = s; __syncthreads();
    for (int st = 64; st > 0; st >>= 1) { if (tid < st) red[tid] += red[tid + st]; __syncthreads(); }
    float mean = red[0] * (1.f / D);
    __syncthreads();
    float vs = 0.f;
#pragma unroll
    for (int c = 0; c < 4; c++) { float dl = v[c] - mean; vs += dl * dl; }
    red[tid] = vs; __syncthreads();
    for (int st = 64; st > 0; st >>= 1) { if (tid < st) red[tid] += red[tid + st]; __syncthreads(); }
    float inv = rsqrtf(red[0] * (1.f / D) + 1e-5f);
#pragma unroll
    for (int c = 0; c < 4; c++) {
        int d = tid + c * 128;
        out[base + d] = (v[c] - mean) * inv * g[d] + bvec[d];
    }
}

// ---------------------------------------------------------------------------
// Misc elementwise kernels
// ---------------------------------------------------------------------------
__global__ void pack_loc_kernel() {      // g_T2[b*LW+i] = g_Sbase[b*N + (N-LW) + i]
    int idx = blockIdx.x * blockDim.x + threadIdx.x;   // over B*LW*D
    int d = idx & (D - 1);
    int row = idx >> 9;
    int b = row >> 6;          // LW = 64
    int i = row & (LW - 1);
    g_T2[idx] = g_Sbase[((size_t)(b * N + (N - LW) + i) << 9) + d];
}

__global__ void expand_local_kernel(const float* __restrict__ packed) {
    size_t idx = (size_t)blockIdx.x * blockDim.x + threadIdx.x;  // over B*N*D
    int d = (int)(idx & (D - 1));
    int row = (int)(idx >> 9);
    int b = row >> 9;          // N = 512
    int n = row & (N - 1);
    float v = 0.f;
    if (n >= N - LW)
        v = packed[(((size_t)b * LW + (n - (N - LW))) << 9) + d];
    g_Slocal[idx] = v;
}

__global__ void sum4_kernel() {
    size_t idx = (size_t)blockIdx.x * blockDim.x + threadIdx.x;  // over B*N*D
    g_Ssum[idx] = g_Sbase[idx] + g_Slocal[idx] + g_Sglob[idx] + g_Scross[idx];
}

__global__ void pred_kernel(const float* __restrict__ F, const float* __restrict__ pw,
                            const float* __restrict__ pb, float* __restrict__ out) {
    int row = blockIdx.x;
    int tid = threadIdx.x;
    const float* x = F + (size_t)row * D;
    float s = 0.f;
    for (int d = tid; d < D; d += 128) s += x[d] * pw[d];
    __shared__ float red[128];
    red[tid] = s; __syncthreads();
    for (int st = 64; st > 0; st >>= 1) { if (tid < st) red[tid] += red[tid + st]; __syncthreads(); }
    if (tid == 0) out[row] = 1.f / (1.f + __expf(-(red[0] + pb[0])));
}

// ---------------------------------------------------------------------------
// Launch
// ---------------------------------------------------------------------------
extern "C" void kernel_launch(void* const* d_in, const int* in_sizes, int n_in,
                              void* d_out, int out_size) {
    (void)in_sizes; (void)n_in; (void)out_size;
    const int*   q     = (const int*)d_in[0];
    const int*   r     = (const int*)d_in[1];
    const int*   qry   = (const int*)d_in[2];
    const float* M_emb = (const float*)d_in[3];
    const float* E_emb = (const float*)d_in[4];
    const float* Pmat  = (const float*)d_in[5];
    const float* biw = (const float*)d_in[6];  const float* bib = (const float*)d_in[7];
    const float* bow = (const float*)d_in[8];  const float* bob = (const float*)d_in[9];
    const float* liw = (const float*)d_in[10]; const float* lib = (const float*)d_in[11];
    const float* low = (const float*)d_in[12]; const float* lob = (const float*)d_in[13];
    const float* giw = (const float*)d_in[14]; const float* gib = (const float*)d_in[15];
    const float* gow = (const float*)d_in[16]; const float* gob = (const float*)d_in[17];
    const float* ciw = (const float*)d_in[18]; const float* cib = (const float*)d_in[19];
    const float* cow = (const float*)d_in[20]; const float* cob = (const float*)d_in[21];
    const float* ln1g = (const float*)d_in[22]; const float* ln1b = (const float*)d_in[23];
    const float* w1 = (const float*)d_in[24];  const float* b1 = (const float*)d_in[25];
    const float* w2 = (const float*)d_in[26];  const float* b2 = (const float*)d_in[27];
    const float* ln2g = (const float*)d_in[28]; const float* ln2b = (const float*)d_in[29];
    const float* pw = (const float*)d_in[30];  const float* pb = (const float*)d_in[31];
    float* out = (float*)d_out;

    float *pM, *pE, *pQ, *pK, *pV, *pO, *pP, *pSb, *pSl, *pSg, *pSc, *pSs, *pT1, *pT2;
    cudaGetSymbolAddress((void**)&pM,  g_M);
    cudaGetSymbolAddress((void**)&pE,  g_E);
    cudaGetSymbolAddress((void**)&pQ,  g_Q);
    cudaGetSymbolAddress((void**)&pK,  g_K);
    cudaGetSymbolAddress((void**)&pV,  g_V);
    cudaGetSymbolAddress((void**)&pO,  g_O);
    cudaGetSymbolAddress((void**)&pP,  g_Prob);
    cudaGetSymbolAddress((void**)&pSb, g_Sbase);
    cudaGetSymbolAddress((void**)&pSl, g_Slocal);
    cudaGetSymbolAddress((void**)&pSg, g_Sglob);
    cudaGetSymbolAddress((void**)&pSc, g_Scross);
    cudaGetSymbolAddress((void**)&pSs, g_Ssum);
    cudaGetSymbolAddress((void**)&pT1, g_T1);
    cudaGetSymbolAddress((void**)&pT2, g_T2);

    auto lin = [&](const float* A, const float* W, const float* bias, float* C, int Mrows,
                   const float* r1, const float* r2, int relu) {
        dim3 g(D / 64, Mrows / 64);
        linear_kernel<<<g, 256>>>(A, W, bias, C, Mrows, D, D, r1, r2, relu);
    };

    // 1. embeddings
    embed_kernel<<<BN_ROWS, 128>>>(q, r, qry, M_emb, E_emb, Pmat);

    // 2. base MHA (Q from E, K/V from M, causal) + attn_w output
    lin(pE, biw,             bib,         pQ, BN_ROWS, nullptr, nullptr, 0);
    lin(pM, biw + D * D,     bib + D,     pK, BN_ROWS, nullptr, nullptr, 0);
    lin(pM, biw + 2 * D * D, bib + 2 * D, pV, BN_ROWS, nullptr, nullptr, 0);
    attn_scores_kernel<<<dim3(N / 64, N / 64, B * H), 256>>>(pQ, pK, pP, N, N, 1);
    softmax_kernel<<<B * H * N, 128>>>(pP, N, N, 1);
    attn_mean_kernel<<<(B * N * N) / 256, 256>>>(pP, out + BN_ROWS);
    attn_pv_kernel<<<dim3(1, N / 64, B * H), 256>>>(pP, pV, pO, N, N, 1);
    lin(pO, bow, bob, pT1, BN_ROWS, nullptr, nullptr, 0);
    ln_kernel<<<BN_ROWS, 128>>>(pT1, pM, pE, ln1g, ln1b, pSb);

    // 3. local MHA on last LW tokens (causal)
    pack_loc_kernel<<<(BLW_ROWS * D) / 256, 256>>>();
    lin(pT2, liw,             lib,         pQ, BLW_ROWS, nullptr, nullptr, 0);
    lin(pT2, liw + D * D,     lib + D,     pK, BLW_ROWS, nullptr, nullptr, 0);
    lin(pT2, liw + 2 * D * D, lib + 2 * D, pV, BLW_ROWS, nullptr, nullptr, 0);
    attn_scores_kernel<<<dim3(1, 1, B * H), 256>>>(pQ, pK, pP, LW, LW, 1);
    softmax_kernel<<<B * H * LW, 128>>>(pP, LW, LW, 1);
    attn_pv_kernel<<<dim3(1, 1, B * H), 256>>>(pP, pV, pO, LW, LW, 1);
    lin(pO, low, lob, pT1, BLW_ROWS, nullptr, nullptr, 0);
    expand_local_kernel<<<(BN_ROWS * D) / 256, 256>>>(pT1);

    // 4. global MHA (self on S_base, causal)
    lin(pSb, giw,             gib,         pQ, BN_ROWS, nullptr, nullptr, 0);
    lin(pSb, giw + D * D,     gib + D,     pK, BN_ROWS, nullptr, nullptr, 0);
    lin(pSb, giw + 2 * D * D, gib + 2 * D, pV, BN_ROWS, nullptr, nullptr, 0);
    attn_scores_kernel<<<dim3(N / 64, N / 64, B * H), 256>>>(pQ, pK, pP, N, N, 1);
    softmax_kernel<<<B * H * N, 128>>>(pP, N, N, 1);
    attn_pv_kernel<<<dim3(1, N / 64, B * H), 256>>>(pP, pV, pO, N, N, 1);
    lin(pO, gow, gob, pSg, BN_ROWS, nullptr, nullptr, 0);

    // 5. cross MHA (Q from S_base, K/V from S_local, no mask)
    lin(pSb, ciw,             cib,         pQ, BN_ROWS, nullptr, nullptr, 0);
    lin(pSl, ciw + D * D,     cib + D,     pK, BN_ROWS, nullptr, nullptr, 0);
    lin(pSl, ciw + 2 * D * D, cib + 2 * D, pV, BN_ROWS, nullptr, nullptr, 0);
    attn_scores_kernel<<<dim3(N / 64, N / 64, B * H), 256>>>(pQ, pK, pP, N, N, 0);
    softmax_kernel<<<B * H * N, 128>>>(pP, N, N, 0);
    attn_pv_kernel<<<dim3(1, N / 64, B * H), 256>>>(pP, pV, pO, N, N, 0);
    lin(pO, cow, cob, pSc, BN_ROWS, nullptr, nullptr, 0);

    // 6. combine + FFN + LN2 + head
    sum4_kernel<<<(BN_ROWS * D) / 256, 256>>>();
    lin(pSs, w1, b1, pT1, BN_ROWS, nullptr, nullptr, 1);   // relu
    lin(pT1, w2, b2, pT2, BN_ROWS, nullptr, nullptr, 0);
    ln_kernel<<<BN_ROWS, 128>>>(pT2, pSs, nullptr, ln2g, ln2b, pT1);
    pred_kernel<<<BN_ROWS, 128>>>(pT1, pw, pb, out);
}

// round 2
// speedup vs baseline: 2.3090x; 2.3090x over previous
#include <cuda_runtime.h>
#include <math.h>
#include <stdint.h>

// ---------------------------------------------------------------------------
// Problem constants
// ---------------------------------------------------------------------------
static constexpr int B  = 16;
static constexpr int N  = 512;
static constexpr int D  = 512;
static constexpr int H  = 8;
static constexpr int HD = 64;     // head dim
static constexpr int LW = 64;
static constexpr int NQ = 10000;
static constexpr int BN_ROWS  = B * N;    // 8192
static constexpr int BLW_ROWS = B * LW;   // 1024

// ---------------------------------------------------------------------------
// Scratch (static device globals -- no allocation allowed)
// ---------------------------------------------------------------------------
__device__ float g_M     [BN_ROWS * D];
__device__ float g_E     [BN_ROWS * D];
__device__ float g_Q     [BN_ROWS * D];
__device__ float g_K     [BN_ROWS * D];
__device__ float g_V     [BN_ROWS * D];
__device__ float g_O     [BN_ROWS * D];
__device__ float g_Prob  [B * H * N * N];   // 64 MB scores/probs
__device__ float g_Sbase [BN_ROWS * D];
__device__ float g_Slocal[BN_ROWS * D];
__device__ float g_Sglob [BN_ROWS * D];
__device__ float g_Scross[BN_ROWS * D];
__device__ float g_Ssum  [BN_ROWS * D];
__device__ float g_T1    [BN_ROWS * D];
__device__ float g_T2    [BN_ROWS * D];

// ---------------------------------------------------------------------------
// Embedding gather: M = M_emb[q + NQ*r] + P[n],  E = E_emb[qry]
// ---------------------------------------------------------------------------
__global__ void embed_kernel(const int* __restrict__ q, const int* __restrict__ r,
                             const int* __restrict__ qry,
                             const float* __restrict__ M_emb,
                             const float* __restrict__ E_emb,
                             const float* __restrict__ P) {
    int row = blockIdx.x;                 // b*N + n
    int n = row & (N - 1);
    int x = q[row] + NQ * r[row];
    int e = qry[row];
    const float* msrc = M_emb + (size_t)x * D;
    const float* esrc = E_emb + (size_t)e * D;
    const float* psrc = P + (size_t)n * D;
    float* mdst = g_M + (size_t)row * D;
    float* edst = g_E + (size_t)row * D;
    for (int d = threadIdx.x; d < D; d += blockDim.x) {
        mdst[d] = msrc[d] + psrc[d];
        edst[d] = esrc[d];
    }
}

// ---------------------------------------------------------------------------
// TF32 tensor-core GEMM for linear layers.
// C[m,n] = sum_k A[m,k]*W[n,k] + bias[n] (+res1+res2) (relu)
// Block tile 128x128, BK=32, 8 warps each computing 64x32 via m16n8k8 tf32 mma.
// Row-major smem tiles with stride 36 (bank-conflict-free frag loads),
// double-buffered cp.async global->smem.
// ---------------------------------------------------------------------------
static constexpr int GBM = 128, GBN = 128, GBK = 32, GSTR = 36;
static constexpr int G_STAGE_FLOATS = (GBM + GBN) * GSTR;        // 9216
static constexpr int G_SMEM_BYTES   = 2 * G_STAGE_FLOATS * 4;    // 73728

__device__ __forceinline__ uint32_t f2tf32(float f) {
    uint32_t u;
    asm("cvt.rna.tf32.f32 %0, %1;" : "=r"(u) : "f"(f));
    return u;
}
__device__ __forceinline__ void cp_async16(uint32_t dst, const void* src) {
    asm volatile("cp.async.cg.shared.global [%0], [%1], 16;" :: "r"(dst), "l"(src));
}
__device__ __forceinline__ void cp_commit() {
    asm volatile("cp.async.commit_group;");
}
__device__ __forceinline__ void mma_tf32(float c[4], uint32_t a0, uint32_t a1,
                                         uint32_t a2, uint32_t a3,
                                         uint32_t b0, uint32_t b1) {
    asm volatile(
        "mma.sync.aligned.m16n8k8.row.col.f32.tf32.tf32.f32 "
        "{%0,%1,%2,%3}, {%4,%5,%6,%7}, {%8,%9}, {%0,%1,%2,%3};"
        : "+f"(c[0]), "+f"(c[1]), "+f"(c[2]), "+f"(c[3])
        : "r"(a0), "r"(a1), "r"(a2), "r"(a3), "r"(b0), "r"(b1));
}

__global__ __launch_bounds__(256, 2)
void linear_tf32_kernel(const float* __restrict__ A, const float* __restrict__ W,
                        const float* __restrict__ bias, float* __restrict__ C,
                        int M, int Nout, int K,
                        const float* __restrict__ res1,
                        const float* __restrict__ res2, int relu) {
    extern __shared__ float sm[];
    const int tid  = threadIdx.x;
    const int lane = tid & 31;
    const int w    = tid >> 5;
    const int g    = lane >> 2;       // groupID
    const int tg   = lane & 3;        // thread in group
    const int wm0  = (w >> 2) * 64;   // warp m offset (0/64)
    const int wn0  = (w & 3) * 32;    // warp n offset (0/32/64/96)
    const int m0   = blockIdx.y * GBM;
    const int n0   = blockIdx.x * GBN;

    const uint32_t sm_u32 = (uint32_t)__cvta_generic_to_shared(sm);

    // tile loader: stage s <- global tile index `t` (k offset = t*GBK)
    auto load_tile = [&](int t, int s) {
        const int k0 = t * GBK;
        uint32_t base = sm_u32 + (uint32_t)(s * G_STAGE_FLOATS) * 4u;
#pragma unroll
        for (int i = 0; i < 4; i++) {              // A part: 128 rows x 8 float4
            int e   = tid + i * 256;
            int row = e >> 3;
            int kc  = (e & 7) * 4;
            cp_async16(base + (uint32_t)(row * GSTR + kc) * 4u,
                       &A[(size_t)(m0 + row) * K + k0 + kc]);
        }
        base += (uint32_t)(GBM * GSTR) * 4u;
#pragma unroll
        for (int i = 0; i < 4; i++) {              // W part
            int e   = tid + i * 256;
            int row = e >> 3;
            int kc  = (e & 7) * 4;
            cp_async16(base + (uint32_t)(row * GSTR + kc) * 4u,
                       &W[(size_t)(n0 + row) * K + k0 + kc]);
        }
        cp_commit();
    };

    float acc[4][4][4] = {};

    const int NT = K / GBK;           // 16
    load_tile(0, 0);
    for (int it = 0; it < NT; ++it) {
        if (it + 1 < NT) {
            load_tile(it + 1, (it + 1) & 1);
            asm volatile("cp.async.wait_group 1;");
        } else {
            asm volatile("cp.async.wait_group 0;");
        }
        __syncthreads();
        const float* As = sm + (it & 1) * G_STAGE_FLOATS;
        const float* Ws = As + GBM * GSTR;
#pragma unroll
        for (int kb = 0; kb < GBK; kb += 8) {
            uint32_t af[4][4], bf[4][2];
#pragma unroll
            for (int tm = 0; tm < 4; tm++) {
                int mr = wm0 + tm * 16 + g;
                af[tm][0] = f2tf32(As[mr * GSTR + kb + tg]);
                af[tm][1] = f2tf32(As[(mr + 8) * GSTR + kb + tg]);
                af[tm][2] = f2tf32(As[mr * GSTR + kb + tg + 4]);
                af[tm][3] = f2tf32(As[(mr + 8) * GSTR + kb + tg + 4]);
            }
#pragma unroll
            for (int tn = 0; tn < 4; tn++) {
                int nr = wn0 + tn * 8 + g;
                bf[tn][0] = f2tf32(Ws[nr * GSTR + kb + tg]);
                bf[tn][1] = f2tf32(Ws[nr * GSTR + kb + tg + 4]);
            }
#pragma unroll
            for (int tm = 0; tm < 4; tm++)
#pragma unroll
                for (int tn = 0; tn < 4; tn++)
                    mma_tf32(acc[tm][tn], af[tm][0], af[tm][1], af[tm][2], af[tm][3],
                             bf[tn][0], bf[tn][1]);
        }
        __syncthreads();
    }

    // epilogue
#pragma unroll
    for (int tm = 0; tm < 4; tm++) {
        int r0 = m0 + wm0 + tm * 16 + g;
        int r1 = r0 + 8;
#pragma unroll
        for (int tn = 0; tn < 4; tn++) {
            int c = n0 + wn0 + tn * 8 + tg * 2;
            float b0 = bias[c], b1 = bias[c + 1];
            size_t o0 = (size_t)r0 * Nout + c;
            size_t o1 = (size_t)r1 * Nout + c;
            float v00 = acc[tm][tn][0] + b0;
            float v01 = acc[tm][tn][1] + b1;
            float v10 = acc[tm][tn][2] + b0;
            float v11 = acc[tm][tn][3] + b1;
            if (res1) { v00 += res1[o0]; v01 += res1[o0 + 1]; v10 += res1[o1]; v11 += res1[o1 + 1]; }
            if (res2) { v00 += res2[o0]; v01 += res2[o0 + 1]; v10 += res2[o1]; v11 += res2[o1 + 1]; }
            if (relu) { v00 = fmaxf(v00, 0.f); v01 = fmaxf(v01, 0.f);
                        v10 = fmaxf(v10, 0.f); v11 = fmaxf(v11, 0.f); }
            *(float2*)&C[o0] = make_float2(v00, v01);
            *(float2*)&C[o1] = make_float2(v10, v11);
        }
    }
}

// ---------------------------------------------------------------------------
// Attention scores: S[z,i,j] = dot(Q[b,i,h*64:], K[b,j,h*64:]) * 0.125
// ---------------------------------------------------------------------------
__global__ void attn_scores_kernel(const float* __restrict__ Q, const float* __restrict__ Kp,
                                   float* __restrict__ S, int Nq, int Nk, int causal) {
    int z = blockIdx.z, b = z / H, h = z - b * H;
    int i0 = blockIdx.y * 64, j0 = blockIdx.x * 64;
    if (causal && j0 > i0 + 63) return;
    const float* Qb = Q + (size_t)b * Nq * D + h * HD;
    const float* Kb = Kp + (size_t)b * Nk * D + h * HD;
    float* Sb = S + (size_t)z * Nq * Nk;
    __shared__ float Qs[16][64];
    __shared__ float Ks[16][64];
    int tid = threadIdx.x, tx = tid & 15, ty = tid >> 4;
    float acc[4][4] = {};
    for (int k0 = 0; k0 < HD; k0 += 16) {
        for (int idx = tid; idx < 64 * 16; idx += 256) {
            int i = idx >> 4, j = idx & 15;
            Qs[j][i] = Qb[(size_t)(i0 + i) * D + k0 + j];
            Ks[j][i] = Kb[(size_t)(j0 + i) * D + k0 + j];
        }
        __syncthreads();
#pragma unroll
        for (int k = 0; k < 16; k++) {
            float a[4], wv[4];
#pragma unroll
            for (int i = 0; i < 4; i++) a[i] = Qs[k][ty * 4 + i];
#pragma unroll
            for (int j = 0; j < 4; j++) wv[j] = Ks[k][tx * 4 + j];
#pragma unroll
            for (int i = 0; i < 4; i++)
#pragma unroll
                for (int j = 0; j < 4; j++) acc[i][j] += a[i] * wv[j];
        }
        __syncthreads();
    }
#pragma unroll
    for (int i = 0; i < 4; i++) {
        int ii = i0 + ty * 4 + i;
#pragma unroll
        for (int j = 0; j < 4; j++)
            Sb[(size_t)ii * Nk + j0 + tx * 4 + j] = acc[i][j] * 0.125f;
    }
}

// ---------------------------------------------------------------------------
// Row softmax with optional causal mask; zero-fills masked tail.
// ---------------------------------------------------------------------------
__global__ void softmax_kernel(float* __restrict__ S, int Nq, int Nk, int causal) {
    int row = blockIdx.x;
    int i = row % Nq;
    float* Sr = S + (size_t)row * Nk;
    int lim = causal ? (i + 1) : Nk;
    int tid = threadIdx.x;
    __shared__ float red[128];
    float mx = -1e30f;
    for (int j = tid; j < lim; j += 128) mx = fmaxf(mx, Sr[j]);
    red[tid] = mx; __syncthreads();
    for (int s = 64; s > 0; s >>= 1) { if (tid < s) red[tid] = fmaxf(red[tid], red[tid + s]); __syncthreads(); }
    mx = red[0]; __syncthreads();
    float sum = 0.f;
    for (int j = tid; j < lim; j += 128) { float e = __expf(Sr[j] - mx); Sr[j] = e; sum += e; }
    red[tid] = sum; __syncthreads();
    for (int s = 64; s > 0; s >>= 1) { if (tid < s) red[tid] += red[tid + s]; __syncthreads(); }
    float inv = 1.f / red[0];
    for (int j = tid; j < lim; j += 128) Sr[j] *= inv;
    for (int j = lim + tid; j < Nk; j += 128) Sr[j] = 0.f;
}

// ---------------------------------------------------------------------------
// attn_w output: mean over heads of base probs -> d_out + B*N
// ---------------------------------------------------------------------------
__global__ void attn_mean_kernel(const float* __restrict__ Pm, float* __restrict__ out) {
    size_t idx = (size_t)blockIdx.x * blockDim.x + threadIdx.x;
    if (idx >= (size_t)B * N * N) return;
    size_t j = idx % N;
    size_t i = (idx / N) % N;
    size_t b = idx / ((size_t)N * N);
    float s = 0.f;
#pragma unroll
    for (int h = 0; h < H; h++)
        s += Pm[(((b * H + h) * N + i) * N) + j];
    out[idx] = s * (1.f / H);
}

// ---------------------------------------------------------------------------
// O = P @ V per (b,h): [Nq,Nk] x [Nk,64] -> O[b,i,h*64+e]. grid(1,Nq/64,B*H)
// ---------------------------------------------------------------------------
__global__ void attn_pv_kernel(const float* __restrict__ Pm, const float* __restrict__ V,
                               float* __restrict__ O, int Nq, int Nk, int causal) {
    int z = blockIdx.z, b = z / H, h = z - b * H;
    int i0 = blockIdx.y * 64;
    const float* Pb = Pm + (size_t)z * Nq * Nk;
    const float* Vb = V + (size_t)b * Nk * D + h * HD;
    float* Ob = O + (size_t)b * Nq * D + h * HD;
    __shared__ float Ps[64][17];
    __shared__ float Vs[16][64];
    int tid = threadIdx.x, tx = tid & 15, ty = tid >> 4;
    float acc[4][4] = {};
    int kend = causal ? min(Nk, i0 + 64) : Nk;
    for (int k0 = 0; k0 < kend; k0 += 16) {
        for (int idx = tid; idx < 64 * 16; idx += 256) {
            int i = idx >> 4, j = idx & 15;
            Ps[i][j] = Pb[(size_t)(i0 + i) * Nk + k0 + j];
        }
        for (int idx = tid; idx < 16 * 64; idx += 256) {
            int k = idx >> 6, e = idx & 63;
            Vs[k][e] = Vb[(size_t)(k0 + k) * D + e];
        }
        __syncthreads();
#pragma unroll
        for (int k = 0; k < 16; k++) {
            float a[4], wv[4];
#pragma unroll
            for (int i = 0; i < 4; i++) a[i] = Ps[ty * 4 + i][k];
#pragma unroll
            for (int j = 0; j < 4; j++) wv[j] = Vs[k][tx * 4 + j];
#pragma unroll
            for (int i = 0; i < 4; i++)
#pragma unroll
                for (int j = 0; j < 4; j++) acc[i][j] += a[i] * wv[j];
        }
        __syncthreads();
    }
#pragma unroll
    for (int i = 0; i < 4; i++)
#pragma unroll
        for (int j = 0; j < 4; j++)
            Ob[(size_t)(i0 + ty * 4 + i) * D + tx * 4 + j] = acc[i][j];
}

// ---------------------------------------------------------------------------
// LayerNorm: out = LN(X + r1? + r2?) * g + b. One block (128 thr) per row.
// ---------------------------------------------------------------------------
__global__ void ln_kernel(const float* __restrict__ X, const float* __restrict__ r1,
                          const float* __restrict__ r2, const float* __restrict__ g,
                          const float* __restrict__ bvec, float* __restrict__ out) {
    int row = blockIdx.x;
    size_t base = (size_t)row * D;
    int tid = threadIdx.x;
    float v[4];
    float s = 0.f;
#pragma unroll
    for (int c = 0; c < 4; c++) {
        int d = tid + c * 128;
        float t = X[base + d];
        if (r1) t += r1[base + d];
        if (r2) t += r2[base + d];
        v[c] = t; s += t;
    }
    __shared__ float red[128];
    red[tid] = s; __syncthreads();
    for (int st = 64; st > 0; st >>= 1) { if (tid < st) red[tid] += red[tid + st]; __syncthreads(); }
    float mean = red[0] * (1.f / D);
    __syncthreads();
    float vs = 0.f;
#pragma unroll
    for (int c = 0; c < 4; c++) { float dl = v[c] - mean; vs += dl * dl; }
    red[tid] = vs; __syncthreads();
    for (int st = 64; st > 0; st >>= 1) { if (tid < st) red[tid] += red[tid + st]; __syncthreads(); }
    float inv = rsqrtf(red[0] * (1.f / D) + 1e-5f);
#pragma unroll
    for (int c = 0; c < 4; c++) {
        int d = tid + c * 128;
        out[base + d] = (v[c] - mean) * inv * g[d] + bvec[d];
    }
}

// ---------------------------------------------------------------------------
// Misc elementwise kernels
// ---------------------------------------------------------------------------
__global__ void pack_loc_kernel() {
    int idx = blockIdx.x * blockDim.x + threadIdx.x;   // over B*LW*D
    int d = idx & (D - 1);
    int row = idx >> 9;
    int b = row >> 6;          // LW = 64
    int i = row & (LW - 1);
    g_T2[idx] = g_Sbase[((size_t)(b * N + (N - LW) + i) << 9) + d];
}

__global__ void expand_local_kernel(const float* __restrict__ packed) {
    size_t idx = (size_t)blockIdx.x * blockDim.x + threadIdx.x;  // over B*N*D
    int d = (int)(idx & (D - 1));
    int row = (int)(idx >> 9);
    int b = row >> 9;          // N = 512
    int n = row & (N - 1);
    float v = 0.f;
    if (n >= N - LW)
        v = packed[(((size_t)b * LW + (n - (N - LW))) << 9) + d];
    g_Slocal[idx] = v;
}

__global__ void sum4_kernel() {
    size_t idx = (size_t)blockIdx.x * blockDim.x + threadIdx.x;  // over B*N*D
    g_Ssum[idx] = g_Sbase[idx] + g_Slocal[idx] + g_Sglob[idx] + g_Scross[idx];
}

__global__ void pred_kernel(const float* __restrict__ F, const float* __restrict__ pw,
                            const float* __restrict__ pb, float* __restrict__ out) {
    int row = blockIdx.x;
    int tid = threadIdx.x;
    const float* x = F + (size_t)row * D;
    float s = 0.f;
    for (int d = tid; d < D; d += 128) s += x[d] * pw[d];
    __shared__ float red[128];
    red[tid] = s; __syncthreads();
    for (int st = 64; st > 0; st >>= 1) { if (tid < st) red[tid] += red[tid + st]; __syncthreads(); }
    if (tid == 0) out[row] = 1.f / (1.f + __expf(-(red[0] + pb[0])));
}

// ---------------------------------------------------------------------------
// Launch
// ---------------------------------------------------------------------------
extern "C" void kernel_launch(void* const* d_in, const int* in_sizes, int n_in,
                              void* d_out, int out_size) {
    (void)in_sizes; (void)n_in; (void)out_size;
    const int*   q     = (const int*)d_in[0];
    const int*   r     = (const int*)d_in[1];
    const int*   qry   = (const int*)d_in[2];
    const float* M_emb = (const float*)d_in[3];
    const float* E_emb = (const float*)d_in[4];
    const float* Pmat  = (const float*)d_in[5];
    const float* biw = (const float*)d_in[6];  const float* bib = (const float*)d_in[7];
    const float* bow = (const float*)d_in[8];  const float* bob = (const float*)d_in[9];
    const float* liw = (const float*)d_in[10]; const float* lib = (const float*)d_in[11];
    const float* low = (const float*)d_in[12]; const float* lob = (const float*)d_in[13];
    const float* giw = (const float*)d_in[14]; const float* gib = (const float*)d_in[15];
    const float* gow = (const float*)d_in[16]; const float* gob = (const float*)d_in[17];
    const float* ciw = (const float*)d_in[18]; const float* cib = (const float*)d_in[19];
    const float* cow = (const float*)d_in[20]; const float* cob = (const float*)d_in[21];
    const float* ln1g = (const float*)d_in[22]; const float* ln1b = (const float*)d_in[23];
    const float* w1 = (const float*)d_in[24];  const float* b1 = (const float*)d_in[25];
    const float* w2 = (const float*)d_in[26];  const float* b2 = (const float*)d_in[27];
    const float* ln2g = (const float*)d_in[28]; const float* ln2b = (const float*)d_in[29];
    const float* pw = (const float*)d_in[30];  const float* pb = (const float*)d_in[31];
    float* out = (float*)d_out;

    float *pM, *pE, *pQ, *pK, *pV, *pO, *pP, *pSb, *pSl, *pSg, *pSc, *pSs, *pT1, *pT2;
    cudaGetSymbolAddress((void**)&pM,  g_M);
    cudaGetSymbolAddress((void**)&pE,  g_E);
    cudaGetSymbolAddress((void**)&pQ,  g_Q);
    cudaGetSymbolAddress((void**)&pK,  g_K);
    cudaGetSymbolAddress((void**)&pV,  g_V);
    cudaGetSymbolAddress((void**)&pO,  g_O);
    cudaGetSymbolAddress((void**)&pP,  g_Prob);
    cudaGetSymbolAddress((void**)&pSb, g_Sbase);
    cudaGetSymbolAddress((void**)&pSl, g_Slocal);
    cudaGetSymbolAddress((void**)&pSg, g_Sglob);
    cudaGetSymbolAddress((void**)&pSc, g_Scross);
    cudaGetSymbolAddress((void**)&pSs, g_Ssum);
    cudaGetSymbolAddress((void**)&pT1, g_T1);
    cudaGetSymbolAddress((void**)&pT2, g_T2);

    cudaFuncSetAttribute(linear_tf32_kernel,
                         cudaFuncAttributeMaxDynamicSharedMemorySize, G_SMEM_BYTES);

    auto lin = [&](const float* A, const float* W, const float* bias, float* C, int Mrows,
                   const float* r1, const float* r2, int relu) {
        dim3 g(D / GBN, Mrows / GBM);
        linear_tf32_kernel<<<g, 256, G_SMEM_BYTES>>>(A, W, bias, C, Mrows, D, D, r1, r2, relu);
    };

    // 1. embeddings
    embed_kernel<<<BN_ROWS, 128>>>(q, r, qry, M_emb, E_emb, Pmat);

    // 2. base MHA (Q from E, K/V from M, causal) + attn_w output
    lin(pE, biw,             bib,         pQ, BN_ROWS, nullptr, nullptr, 0);
    lin(pM, biw + D * D,     bib + D,     pK, BN_ROWS, nullptr, nullptr, 0);
    lin(pM, biw + 2 * D * D, bib + 2 * D, pV, BN_ROWS, nullptr, nullptr, 0);
    attn_scores_kernel<<<dim3(N / 64, N / 64, B * H), 256>>>(pQ, pK, pP, N, N, 1);
    softmax_kernel<<<B * H * N, 128>>>(pP, N, N, 1);
    attn_mean_kernel<<<(B * N * N) / 256, 256>>>(pP, out + BN_ROWS);
    attn_pv_kernel<<<dim3(1, N / 64, B * H), 256>>>(pP, pV, pO, N, N, 1);
    lin(pO, bow, bob, pT1, BN_ROWS, nullptr, nullptr, 0);
    ln_kernel<<<BN_ROWS, 128>>>(pT1, pM, pE, ln1g, ln1b, pSb);

    // 3. local MHA on last LW tokens (causal)
    pack_loc_kernel<<<(BLW_ROWS * D) / 256, 256>>>();
    lin(pT2, liw,             lib,         pQ, BLW_ROWS, nullptr, nullptr, 0);
    lin(pT2, liw + D * D,     lib + D,     pK, BLW_ROWS, nullptr, nullptr, 0);
    lin(pT2, liw + 2 * D * D, lib + 2 * D, pV, BLW_ROWS, nullptr, nullptr, 0);
    attn_scores_kernel<<<dim3(1, 1, B * H), 256>>>(pQ, pK, pP, LW, LW, 1);
    softmax_kernel<<<B * H * LW, 128>>>(pP, LW, LW, 1);
    attn_pv_kernel<<<dim3(1, 1, B * H), 256>>>(pP, pV, pO, LW, LW, 1);
    lin(pO, low, lob, pT1, BLW_ROWS, nullptr, nullptr, 0);
    expand_local_kernel<<<(BN_ROWS * D) / 256, 256>>>(pT1);

    // 4. global MHA (self on S_base, causal)
    lin(pSb, giw,             gib,         pQ, BN_ROWS, nullptr, nullptr, 0);
    lin(pSb, giw + D * D,     gib + D,     pK, BN_ROWS, nullptr, nullptr, 0);
    lin(pSb, giw + 2 * D * D, gib + 2 * D, pV, BN_ROWS, nullptr, nullptr, 0);
    attn_scores_kernel<<<dim3(N / 64, N / 64, B * H), 256>>>(pQ, pK, pP, N, N, 1);
    softmax_kernel<<<B * H * N, 128>>>(pP, N, N, 1);
    attn_pv_kernel<<<dim3(1, N / 64, B * H), 256>>>(pP, pV, pO, N, N, 1);
    lin(pO, gow, gob, pSg, BN_ROWS, nullptr, nullptr, 0);

    // 5. cross MHA (Q from S_base, K/V from S_local, no mask)
    lin(pSb, ciw,             cib,         pQ, BN_ROWS, nullptr, nullptr, 0);
    lin(pSl, ciw + D * D,     cib + D,     pK, BN_ROWS, nullptr, nullptr, 0);
    lin(pSl, ciw + 2 * D * D, cib + 2 * D, pV, BN_ROWS, nullptr, nullptr, 0);
    attn_scores_kernel<<<dim3(N / 64, N / 64, B * H), 256>>>(pQ, pK, pP, N, N, 0);
    softmax_kernel<<<B * H * N, 128>>>(pP, N, N, 0);
    attn_pv_kernel<<<dim3(1, N / 64, B * H), 256>>>(pP, pV, pO, N, N, 0);
    lin(pO, cow, cob, pSc, BN_ROWS, nullptr, nullptr, 0);

    // 6. combine + FFN + LN2 + head
    sum4_kernel<<<(BN_ROWS * D) / 256, 256>>>();
    lin(pSs, w1, b1, pT1, BN_ROWS, nullptr, nullptr, 1);   // relu
    lin(pT1, w2, b2, pT2, BN_ROWS, nullptr, nullptr, 0);
    ln_kernel<<<BN_ROWS, 128>>>(pT2, pSs, nullptr, ln2g, ln2b, pT1);
    pred_kernel<<<BN_ROWS, 128>>>(pT1, pw, pb, out);
}

// round 3
// speedup vs baseline: 4.2406x; 1.8366x over previous
#include <cuda_runtime.h>
#include <math.h>
#include <stdint.h>

// ---------------------------------------------------------------------------
// Problem constants
// ---------------------------------------------------------------------------
static constexpr int B  = 16;
static constexpr int N  = 512;
static constexpr int D  = 512;
static constexpr int H  = 8;
static constexpr int HD = 64;     // head dim
static constexpr int LW = 64;
static constexpr int NQ = 10000;
static constexpr int BN_ROWS  = B * N;    // 8192
static constexpr int BLW_ROWS = B * LW;   // 1024

// ---------------------------------------------------------------------------
// Scratch (static device globals -- no allocation allowed)
// ---------------------------------------------------------------------------
__device__ float g_M     [BN_ROWS * D];
__device__ float g_E     [BN_ROWS * D];
__device__ float g_Q     [BN_ROWS * D];
__device__ float g_K     [BN_ROWS * D];
__device__ float g_V     [BN_ROWS * D];
__device__ float g_O     [BN_ROWS * D];
__device__ float g_Prob  [B * H * N * N];   // 64 MB scores/probs
__device__ float g_Sbase [BN_ROWS * D];
__device__ float g_Slocal[BN_ROWS * D];
__device__ float g_Sglob [BN_ROWS * D];
__device__ float g_Scross[BN_ROWS * D];
__device__ float g_Ssum  [BN_ROWS * D];
__device__ float g_T1    [BN_ROWS * D];
__device__ float g_T2    [BN_ROWS * D];

// ---------------------------------------------------------------------------
// Common MMA helpers
// ---------------------------------------------------------------------------
__device__ __forceinline__ uint32_t f2tf32(float f) {
    uint32_t u;
    asm("cvt.rna.tf32.f32 %0, %1;" : "=r"(u) : "f"(f));
    return u;
}
__device__ __forceinline__ void cp_async16(uint32_t dst, const void* src) {
    asm volatile("cp.async.cg.shared.global [%0], [%1], 16;" :: "r"(dst), "l"(src));
}
__device__ __forceinline__ void cp_commit() {
    asm volatile("cp.async.commit_group;");
}
__device__ __forceinline__ void mma_tf32(float c[4], uint32_t a0, uint32_t a1,
                                         uint32_t a2, uint32_t a3,
                                         uint32_t b0, uint32_t b1) {
    asm volatile(
        "mma.sync.aligned.m16n8k8.row.col.f32.tf32.tf32.f32 "
        "{%0,%1,%2,%3}, {%4,%5,%6,%7}, {%8,%9}, {%0,%1,%2,%3};"
        : "+f"(c[0]), "+f"(c[1]), "+f"(c[2]), "+f"(c[3])
        : "r"(a0), "r"(a1), "r"(a2), "r"(a3), "r"(b0), "r"(b1));
}

// ---------------------------------------------------------------------------
// Embedding gather: M = M_emb[q + NQ*r] + P[n],  E = E_emb[qry]
// ---------------------------------------------------------------------------
__global__ void embed_kernel(const int* __restrict__ q, const int* __restrict__ r,
                             const int* __restrict__ qry,
                             const float* __restrict__ M_emb,
                             const float* __restrict__ E_emb,
                             const float* __restrict__ P) {
    int row = blockIdx.x;
    int n = row & (N - 1);
    int x = q[row] + NQ * r[row];
    int e = qry[row];
    const float* msrc = M_emb + (size_t)x * D;
    const float* esrc = E_emb + (size_t)e * D;
    const float* psrc = P + (size_t)n * D;
    float* mdst = g_M + (size_t)row * D;
    float* edst = g_E + (size_t)row * D;
    for (int d = threadIdx.x; d < D; d += blockDim.x) {
        mdst[d] = msrc[d] + psrc[d];
        edst[d] = esrc[d];
    }
}

// ---------------------------------------------------------------------------
// TF32 tensor-core GEMM for linear layers. 128x128 tile, BK=32, 8 warps.
// ---------------------------------------------------------------------------
static constexpr int GBM = 128, GBN = 128, GBK = 32, GSTR = 36;
static constexpr int G_STAGE_FLOATS = (GBM + GBN) * GSTR;        // 9216
static constexpr int G_SMEM_BYTES   = 2 * G_STAGE_FLOATS * 4;    // 73728

__global__ __launch_bounds__(256, 2)
void linear_tf32_kernel(const float* __restrict__ A, const float* __restrict__ W,
                        const float* __restrict__ bias, float* __restrict__ C,
                        int M, int Nout, int K,
                        const float* __restrict__ res1,
                        const float* __restrict__ res2, int relu) {
    extern __shared__ float sm[];
    const int tid  = threadIdx.x;
    const int lane = tid & 31;
    const int w    = tid >> 5;
    const int g    = lane >> 2;
    const int tg   = lane & 3;
    const int wm0  = (w >> 2) * 64;
    const int wn0  = (w & 3) * 32;
    const int m0   = blockIdx.y * GBM;
    const int n0   = blockIdx.x * GBN;

    const uint32_t sm_u32 = (uint32_t)__cvta_generic_to_shared(sm);

    auto load_tile = [&](int t, int s) {
        const int k0 = t * GBK;
        uint32_t base = sm_u32 + (uint32_t)(s * G_STAGE_FLOATS) * 4u;
#pragma unroll
        for (int i = 0; i < 4; i++) {
            int e   = tid + i * 256;
            int row = e >> 3;
            int kc  = (e & 7) * 4;
            cp_async16(base + (uint32_t)(row * GSTR + kc) * 4u,
                       &A[(size_t)(m0 + row) * K + k0 + kc]);
        }
        base += (uint32_t)(GBM * GSTR) * 4u;
#pragma unroll
        for (int i = 0; i < 4; i++) {
            int e   = tid + i * 256;
            int row = e >> 3;
            int kc  = (e & 7) * 4;
            cp_async16(base + (uint32_t)(row * GSTR + kc) * 4u,
                       &W[(size_t)(n0 + row) * K + k0 + kc]);
        }
        cp_commit();
    };

    float acc[4][4][4] = {};
    const int NT = K / GBK;
    load_tile(0, 0);
    for (int it = 0; it < NT; ++it) {
        if (it + 1 < NT) {
            load_tile(it + 1, (it + 1) & 1);
            asm volatile("cp.async.wait_group 1;");
        } else {
            asm volatile("cp.async.wait_group 0;");
        }
        __syncthreads();
        const float* As = sm + (it & 1) * G_STAGE_FLOATS;
        const float* Ws = As + GBM * GSTR;
#pragma unroll
        for (int kb = 0; kb < GBK; kb += 8) {
            uint32_t af[4][4], bf[4][2];
#pragma unroll
            for (int tm = 0; tm < 4; tm++) {
                int mr = wm0 + tm * 16 + g;
                af[tm][0] = f2tf32(As[mr * GSTR + kb + tg]);
                af[tm][1] = f2tf32(As[(mr + 8) * GSTR + kb + tg]);
                af[tm][2] = f2tf32(As[mr * GSTR + kb + tg + 4]);
                af[tm][3] = f2tf32(As[(mr + 8) * GSTR + kb + tg + 4]);
            }
#pragma unroll
            for (int tn = 0; tn < 4; tn++) {
                int nr = wn0 + tn * 8 + g;
                bf[tn][0] = f2tf32(Ws[nr * GSTR + kb + tg]);
                bf[tn][1] = f2tf32(Ws[nr * GSTR + kb + tg + 4]);
            }
#pragma unroll
            for (int tm = 0; tm < 4; tm++)
#pragma unroll
                for (int tn = 0; tn < 4; tn++)
                    mma_tf32(acc[tm][tn], af[tm][0], af[tm][1], af[tm][2], af[tm][3],
                             bf[tn][0], bf[tn][1]);
        }
        __syncthreads();
    }

#pragma unroll
    for (int tm = 0; tm < 4; tm++) {
        int r0 = m0 + wm0 + tm * 16 + g;
        int r1 = r0 + 8;
#pragma unroll
        for (int tn = 0; tn < 4; tn++) {
            int c = n0 + wn0 + tn * 8 + tg * 2;
            float b0 = bias[c], b1 = bias[c + 1];
            size_t o0 = (size_t)r0 * Nout + c;
            size_t o1 = (size_t)r1 * Nout + c;
            float v00 = acc[tm][tn][0] + b0;
            float v01 = acc[tm][tn][1] + b1;
            float v10 = acc[tm][tn][2] + b0;
            float v11 = acc[tm][tn][3] + b1;
            if (res1) { v00 += res1[o0]; v01 += res1[o0 + 1]; v10 += res1[o1]; v11 += res1[o1 + 1]; }
            if (res2) { v00 += res2[o0]; v01 += res2[o0 + 1]; v10 += res2[o1]; v11 += res2[o1 + 1]; }
            if (relu) { v00 = fmaxf(v00, 0.f); v01 = fmaxf(v01, 0.f);
                        v10 = fmaxf(v10, 0.f); v11 = fmaxf(v11, 0.f); }
            *(float2*)&C[o0] = make_float2(v00, v01);
            *(float2*)&C[o1] = make_float2(v10, v11);
        }
    }
}

// ---------------------------------------------------------------------------
// TF32 attention scores: S[z,i,j] = dot(Q[b,i,h*64:], K[b,j,h*64:]) * 0.125
// 128x128 block tile, K = HD = 64 (2 x BK=32). grid (N/128, N/128, B*H).
// Causal: tiles fully above the diagonal skipped (softmax ignores them).
// ---------------------------------------------------------------------------
__global__ __launch_bounds__(256, 2)
void attn_scores_tf32_kernel(const float* __restrict__ Q, const float* __restrict__ Kp,
                             float* __restrict__ S, int causal) {
    const int z = blockIdx.z, b = z >> 3, h = z & 7;
    const int i0 = blockIdx.y * 128, j0 = blockIdx.x * 128;
    if (causal && j0 > i0 + 127) return;
    const float* Qb = Q + (size_t)b * N * D + h * HD;
    const float* Kb = Kp + (size_t)b * N * D + h * HD;
    float* Sb = S + (size_t)z * N * N;

    extern __shared__ float sm[];
    const int tid  = threadIdx.x;
    const int lane = tid & 31;
    const int w    = tid >> 5;
    const int g    = lane >> 2;
    const int tg   = lane & 3;
    const int wm0  = (w >> 2) * 64;
    const int wn0  = (w & 3) * 32;
    const uint32_t sm_u32 = (uint32_t)__cvta_generic_to_shared(sm);

    auto load_tile = [&](int t, int s) {
        const int k0 = t * GBK;
        uint32_t base = sm_u32 + (uint32_t)(s * G_STAGE_FLOATS) * 4u;
#pragma unroll
        for (int i = 0; i < 4; i++) {
            int e   = tid + i * 256;
            int row = e >> 3;
            int kc  = (e & 7) * 4;
            cp_async16(base + (uint32_t)(row * GSTR + kc) * 4u,
                       &Qb[(size_t)(i0 + row) * D + k0 + kc]);
        }
        base += (uint32_t)(GBM * GSTR) * 4u;
#pragma unroll
        for (int i = 0; i < 4; i++) {
            int e   = tid + i * 256;
            int row = e >> 3;
            int kc  = (e & 7) * 4;
            cp_async16(base + (uint32_t)(row * GSTR + kc) * 4u,
                       &Kb[(size_t)(j0 + row) * D + k0 + kc]);
        }
        cp_commit();
    };

    float acc[4][4][4] = {};
    const int NT = HD / GBK;   // 2
    load_tile(0, 0);
    for (int it = 0; it < NT; ++it) {
        if (it + 1 < NT) {
            load_tile(it + 1, (it + 1) & 1);
            asm volatile("cp.async.wait_group 1;");
        } else {
            asm volatile("cp.async.wait_group 0;");
        }
        __syncthreads();
        const float* As = sm + (it & 1) * G_STAGE_FLOATS;
        const float* Ws = As + GBM * GSTR;
#pragma unroll
        for (int kb = 0; kb < GBK; kb += 8) {
            uint32_t af[4][4], bf[4][2];
#pragma unroll
            for (int tm = 0; tm < 4; tm++) {
                int mr = wm0 + tm * 16 + g;
                af[tm][0] = f2tf32(As[mr * GSTR + kb + tg]);
                af[tm][1] = f2tf32(As[(mr + 8) * GSTR + kb + tg]);
                af[tm][2] = f2tf32(As[mr * GSTR + kb + tg + 4]);
                af[tm][3] = f2tf32(As[(mr + 8) * GSTR + kb + tg + 4]);
            }
#pragma unroll
            for (int tn = 0; tn < 4; tn++) {
                int nr = wn0 + tn * 8 + g;
                bf[tn][0] = f2tf32(Ws[nr * GSTR + kb + tg]);
                bf[tn][1] = f2tf32(Ws[nr * GSTR + kb + tg + 4]);
            }
#pragma unroll
            for (int tm = 0; tm < 4; tm++)
#pragma unroll
                for (int tn = 0; tn < 4; tn++)
                    mma_tf32(acc[tm][tn], af[tm][0], af[tm][1], af[tm][2], af[tm][3],
                             bf[tn][0], bf[tn][1]);
        }
        __syncthreads();
    }

#pragma unroll
    for (int tm = 0; tm < 4; tm++) {
        int r0 = i0 + wm0 + tm * 16 + g;
        int r1 = r0 + 8;
#pragma unroll
        for (int tn = 0; tn < 4; tn++) {
            int c = j0 + wn0 + tn * 8 + tg * 2;
            *(float2*)&Sb[(size_t)r0 * N + c] =
                make_float2(acc[tm][tn][0] * 0.125f, acc[tm][tn][1] * 0.125f);
            *(float2*)&Sb[(size_t)r1 * N + c] =
                make_float2(acc[tm][tn][2] * 0.125f, acc[tm][tn][3] * 0.125f);
        }
    }
}

// ---------------------------------------------------------------------------
// TF32 PV: O[b,i,h*64+e] = sum_j P[z,i,j] * V[b,j,h*64+e]
// 128x64 block tile, K loop over Nk (truncated at i0+128 for causal).
// 8 warps, warp tile 32x32. grid (1, N/128, B*H).
// ---------------------------------------------------------------------------
static constexpr int PASTR = 36, PVSTR = 68;
static constexpr int P_STAGE_FLOATS = 128 * PASTR + 32 * PVSTR;  // 6784
static constexpr int P_SMEM_BYTES   = 2 * P_STAGE_FLOATS * 4;    // 54272

__global__ __launch_bounds__(256, 2)
void attn_pv_tf32_kernel(const float* __restrict__ Pm, const float* __restrict__ V,
                         float* __restrict__ O, int causal) {
    const int z = blockIdx.z, b = z >> 3, h = z & 7;
    const int i0 = blockIdx.y * 128;
    const float* Pb = Pm + (size_t)z * N * N;
    const float* Vb = V + (size_t)b * N * D + h * HD;
    float* Ob = O + (size_t)b * N * D + h * HD;

    extern __shared__ float sm[];
    const int tid  = threadIdx.x;
    const int lane = tid & 31;
    const int w    = tid >> 5;
    const int g    = lane >> 2;
    const int tg   = lane & 3;
    const int wm0  = (w >> 1) * 32;   // 0..96
    const int wn0  = (w & 1) * 32;    // 0/32
    const uint32_t sm_u32 = (uint32_t)__cvta_generic_to_shared(sm);

    auto load_tile = [&](int t, int s) {
        const int k0 = t * 32;
        uint32_t base = sm_u32 + (uint32_t)(s * P_STAGE_FLOATS) * 4u;
#pragma unroll
        for (int i = 0; i < 4; i++) {          // P tile: 128 rows x 32 k
            int e   = tid + i * 256;
            int row = e >> 3;
            int kc  = (e & 7) * 4;
            cp_async16(base + (uint32_t)(row * PASTR + kc) * 4u,
                       &Pb[(size_t)(i0 + row) * N + k0 + kc]);
        }
        base += (uint32_t)(128 * PASTR) * 4u;
#pragma unroll
        for (int i = 0; i < 2; i++) {          // V tile: 32 rows x 64 e
            int e   = tid + i * 256;
            int row = e >> 4;
            int ec  = (e & 15) * 4;
            cp_async16(base + (uint32_t)(row * PVSTR + ec) * 4u,
                       &Vb[(size_t)(k0 + row) * D + ec]);
        }
        cp_commit();
    };

    float acc[2][4][4] = {};
    const int kend = causal ? min(N, i0 + 128) : N;
    const int NT = kend / 32;
    load_tile(0, 0);
    for (int it = 0; it < NT; ++it) {
        if (it + 1 < NT) {
            load_tile(it + 1, (it + 1) & 1);
            asm volatile("cp.async.wait_group 1;");
        } else {
            asm volatile("cp.async.wait_group 0;");
        }
        __syncthreads();
        const float* As = sm + (it & 1) * P_STAGE_FLOATS;
        const float* Vs = As + 128 * PASTR;
#pragma unroll
        for (int kb = 0; kb < 32; kb += 8) {
            uint32_t af[2][4], bf[4][2];
#pragma unroll
            for (int tm = 0; tm < 2; tm++) {
                int mr = wm0 + tm * 16 + g;
                af[tm][0] = f2tf32(As[mr * PASTR + kb + tg]);
                af[tm][1] = f2tf32(As[(mr + 8) * PASTR + kb + tg]);
                af[tm][2] = f2tf32(As[mr * PASTR + kb + tg + 4]);
                af[tm][3] = f2tf32(As[(mr + 8) * PASTR + kb + tg + 4]);
            }
#pragma unroll
            for (int tn = 0; tn < 4; tn++) {
                int nr = wn0 + tn * 8 + g;
                bf[tn][0] = f2tf32(Vs[(kb + tg) * PVSTR + nr]);
                bf[tn][1] = f2tf32(Vs[(kb + tg + 4) * PVSTR + nr]);
            }
#pragma unroll
            for (int tm = 0; tm < 2; tm++)
#pragma unroll
                for (int tn = 0; tn < 4; tn++)
                    mma_tf32(acc[tm][tn], af[tm][0], af[tm][1], af[tm][2], af[tm][3],
                             bf[tn][0], bf[tn][1]);
        }
        __syncthreads();
    }

#pragma unroll
    for (int tm = 0; tm < 2; tm++) {
        int r0 = i0 + wm0 + tm * 16 + g;
        int r1 = r0 + 8;
#pragma unroll
        for (int tn = 0; tn < 4; tn++) {
            int c = wn0 + tn * 8 + tg * 2;
            *(float2*)&Ob[(size_t)r0 * D + c] = make_float2(acc[tm][tn][0], acc[tm][tn][1]);
            *(float2*)&Ob[(size_t)r1 * D + c] = make_float2(acc[tm][tn][2], acc[tm][tn][3]);
        }
    }
}

// ---------------------------------------------------------------------------
// SIMT attention kernels (kept for the tiny LW=64 local attention)
// ---------------------------------------------------------------------------
__global__ void attn_scores_kernel(const float* __restrict__ Q, const float* __restrict__ Kp,
                                   float* __restrict__ S, int Nq, int Nk, int causal) {
    int z = blockIdx.z, b = z / H, h = z - b * H;
    int i0 = blockIdx.y * 64, j0 = blockIdx.x * 64;
    if (causal && j0 > i0 + 63) return;
    const float* Qb = Q + (size_t)b * Nq * D + h * HD;
    const float* Kb = Kp + (size_t)b * Nk * D + h * HD;
    float* Sb = S + (size_t)z * Nq * Nk;
    __shared__ float Qs[16][64];
    __shared__ float Ks[16][64];
    int tid = threadIdx.x, tx = tid & 15, ty = tid >> 4;
    float acc[4][4] = {};
    for (int k0 = 0; k0 < HD; k0 += 16) {
        for (int idx = tid; idx < 64 * 16; idx += 256) {
            int i = idx >> 4, j = idx & 15;
            Qs[j][i] = Qb[(size_t)(i0 + i) * D + k0 + j];
            Ks[j][i] = Kb[(size_t)(j0 + i) * D + k0 + j];
        }
        __syncthreads();
#pragma unroll
        for (int k = 0; k < 16; k++) {
            float a[4], wv[4];
#pragma unroll
            for (int i = 0; i < 4; i++) a[i] = Qs[k][ty * 4 + i];
#pragma unroll
            for (int j = 0; j < 4; j++) wv[j] = Ks[k][tx * 4 + j];
#pragma unroll
            for (int i = 0; i < 4; i++)
#pragma unroll
                for (int j = 0; j < 4; j++) acc[i][j] += a[i] * wv[j];
        }
        __syncthreads();
    }
#pragma unroll
    for (int i = 0; i < 4; i++) {
        int ii = i0 + ty * 4 + i;
#pragma unroll
        for (int j = 0; j < 4; j++)
            Sb[(size_t)ii * Nk + j0 + tx * 4 + j] = acc[i][j] * 0.125f;
    }
}

__global__ void attn_pv_kernel(const float* __restrict__ Pm, const float* __restrict__ V,
                               float* __restrict__ O, int Nq, int Nk, int causal) {
    int z = blockIdx.z, b = z / H, h = z - b * H;
    int i0 = blockIdx.y * 64;
    const float* Pb = Pm + (size_t)z * Nq * Nk;
    const float* Vb = V + (size_t)b * Nk * D + h * HD;
    float* Ob = O + (size_t)b * Nq * D + h * HD;
    __shared__ float Ps[64][17];
    __shared__ float Vs[16][64];
    int tid = threadIdx.x, tx = tid & 15, ty = tid >> 4;
    float acc[4][4] = {};
    int kend = causal ? min(Nk, i0 + 64) : Nk;
    for (int k0 = 0; k0 < kend; k0 += 16) {
        for (int idx = tid; idx < 64 * 16; idx += 256) {
            int i = idx >> 4, j = idx & 15;
            Ps[i][j] = Pb[(size_t)(i0 + i) * Nk + k0 + j];
        }
        for (int idx = tid; idx < 16 * 64; idx += 256) {
            int k = idx >> 6, e = idx & 63;
            Vs[k][e] = Vb[(size_t)(k0 + k) * D + e];
        }
        __syncthreads();
#pragma unroll
        for (int k = 0; k < 16; k++) {
            float a[4], wv[4];
#pragma unroll
            for (int i = 0; i < 4; i++) a[i] = Ps[ty * 4 + i][k];
#pragma unroll
            for (int j = 0; j < 4; j++) wv[j] = Vs[k][tx * 4 + j];
#pragma unroll
            for (int i = 0; i < 4; i++)
#pragma unroll
                for (int j = 0; j < 4; j++) acc[i][j] += a[i] * wv[j];
        }
        __syncthreads();
    }
#pragma unroll
    for (int i = 0; i < 4; i++)
#pragma unroll
        for (int j = 0; j < 4; j++)
            Ob[(size_t)(i0 + ty * 4 + i) * D + tx * 4 + j] = acc[i][j];
}

// ---------------------------------------------------------------------------
// Register softmax: single global read + single write. Zeroes masked tail.
// One block (128 thr) per row; supports Nk <= 512.
// ---------------------------------------------------------------------------
__global__ void softmax_kernel(float* __restrict__ S, int Nq, int Nk, int causal) {
    int row = blockIdx.x;
    int i = row % Nq;
    float* Sr = S + (size_t)row * Nk;
    int lim = causal ? (i + 1) : Nk;
    int tid = threadIdx.x;
    float v[4];
    float mx = -1e30f;
#pragma unroll
    for (int c = 0; c < 4; c++) {
        int j = tid + c * 128;
        v[c] = (j < lim) ? Sr[j] : -1e30f;
        mx = fmaxf(mx, v[c]);
    }
    __shared__ float red[128];
    red[tid] = mx; __syncthreads();
    for (int s = 64; s > 0; s >>= 1) { if (tid < s) red[tid] = fmaxf(red[tid], red[tid + s]); __syncthreads(); }
    mx = red[0]; __syncthreads();
    float sum = 0.f;
#pragma unroll
    for (int c = 0; c < 4; c++) {
        int j = tid + c * 128;
        float e = (j < lim) ? __expf(v[c] - mx) : 0.f;
        v[c] = e; sum += e;
    }
    red[tid] = sum; __syncthreads();
    for (int s = 64; s > 0; s >>= 1) { if (tid < s) red[tid] += red[tid + s]; __syncthreads(); }
    float inv = 1.f / red[0];
#pragma unroll
    for (int c = 0; c < 4; c++) {
        int j = tid + c * 128;
        if (j < Nk) Sr[j] = v[c] * inv;
    }
}

// ---------------------------------------------------------------------------
// attn_w output: mean over heads of base probs -> d_out + B*N
// ---------------------------------------------------------------------------
__global__ void attn_mean_kernel(const float* __restrict__ Pm, float* __restrict__ out) {
    size_t idx = (size_t)blockIdx.x * blockDim.x + threadIdx.x;
    if (idx >= (size_t)B * N * N) return;
    size_t j = idx % N;
    size_t i = (idx / N) % N;
    size_t b = idx / ((size_t)N * N);
    float s = 0.f;
#pragma unroll
    for (int h = 0; h < H; h++)
        s += Pm[(((b * H + h) * N + i) * N) + j];
    out[idx] = s * (1.f / H);
}

// ---------------------------------------------------------------------------
// LayerNorm: out = LN(X + r1? + r2?) * g + b.
// ---------------------------------------------------------------------------
__global__ void ln_kernel(const float* __restrict__ X, const float* __restrict__ r1,
                          const float* __restrict__ r2, const float* __restrict__ g,
                          const float* __restrict__ bvec, float* __restrict__ out) {
    int row = blockIdx.x;
    size_t base = (size_t)row * D;
    int tid = threadIdx.x;
    float v[4];
    float s = 0.f;
#pragma unroll
    for (int c = 0; c < 4; c++) {
        int d = tid + c * 128;
        float t = X[base + d];
        if (r1) t += r1[base + d];
        if (r2) t += r2[base + d];
        v[c] = t; s += t;
    }
    __shared__ float red[128];
    red[tid] = s; __syncthreads();
    for (int st = 64; st > 0; st >>= 1) { if (tid < st) red[tid] += red[tid + st]; __syncthreads(); }
    float mean = red[0] * (1.f / D);
    __syncthreads();
    float vs = 0.f;
#pragma unroll
    for (int c = 0; c < 4; c++) { float dl = v[c] - mean; vs += dl * dl; }
    red[tid] = vs; __syncthreads();
    for (int st = 64; st > 0; st >>= 1) { if (tid < st) red[tid] += red[tid + st]; __syncthreads(); }
    float inv = rsqrtf(red[0] * (1.f / D) + 1e-5f);
#pragma unroll
    for (int c = 0; c < 4; c++) {
        int d = tid + c * 128;
        out[base + d] = (v[c] - mean) * inv * g[d] + bvec[d];
    }
}

// ---------------------------------------------------------------------------
// Misc elementwise kernels
// ---------------------------------------------------------------------------
__global__ void pack_loc_kernel() {
    int idx = blockIdx.x * blockDim.x + threadIdx.x;
    int d = idx & (D - 1);
    int row = idx >> 9;
    int b = row >> 6;
    int i = row & (LW - 1);
    g_T2[idx] = g_Sbase[((size_t)(b * N + (N - LW) + i) << 9) + d];
}

__global__ void expand_local_kernel(const float* __restrict__ packed) {
    size_t idx = (size_t)blockIdx.x * blockDim.x + threadIdx.x;
    int d = (int)(idx & (D - 1));
    int row = (int)(idx >> 9);
    int b = row >> 9;
    int n = row & (N - 1);
    float v = 0.f;
    if (n >= N - LW)
        v = packed[(((size_t)b * LW + (n - (N - LW))) << 9) + d];
    g_Slocal[idx] = v;
}

__global__ void sum4_kernel() {
    size_t idx = (size_t)blockIdx.x * blockDim.x + threadIdx.x;
    g_Ssum[idx] = g_Sbase[idx] + g_Slocal[idx] + g_Sglob[idx] + g_Scross[idx];
}

__global__ void pred_kernel(const float* __restrict__ F, const float* __restrict__ pw,
                            const float* __restrict__ pb, float* __restrict__ out) {
    int row = blockIdx.x;
    int tid = threadIdx.x;
    const float* x = F + (size_t)row * D;
    float s = 0.f;
    for (int d = tid; d < D; d += 128) s += x[d] * pw[d];
    __shared__ float red[128];
    red[tid] = s; __syncthreads();
    for (int st = 64; st > 0; st >>= 1) { if (tid < st) red[tid] += red[tid + st]; __syncthreads(); }
    if (tid == 0) out[row] = 1.f / (1.f + __expf(-(red[0] + pb[0])));
}

// ---------------------------------------------------------------------------
// Launch
// ---------------------------------------------------------------------------
extern "C" void kernel_launch(void* const* d_in, const int* in_sizes, int n_in,
                              void* d_out, int out_size) {
    (void)in_sizes; (void)n_in; (void)out_size;
    const int*   q     = (const int*)d_in[0];
    const int*   r     = (const int*)d_in[1];
    const int*   qry   = (const int*)d_in[2];
    const float* M_emb = (const float*)d_in[3];
    const float* E_emb = (const float*)d_in[4];
    const float* Pmat  = (const float*)d_in[5];
    const float* biw = (const float*)d_in[6];  const float* bib = (const float*)d_in[7];
    const float* bow = (const float*)d_in[8];  const float* bob = (const float*)d_in[9];
    const float* liw = (const float*)d_in[10]; const float* lib = (const float*)d_in[11];
    const float* low = (const float*)d_in[12]; const float* lob = (const float*)d_in[13];
    const float* giw = (const float*)d_in[14]; const float* gib = (const float*)d_in[15];
    const float* gow = (const float*)d_in[16]; const float* gob = (const float*)d_in[17];
    const float* ciw = (const float*)d_in[18]; const float* cib = (const float*)d_in[19];
    const float* cow = (const float*)d_in[20]; const float* cob = (const float*)d_in[21];
    const float* ln1g = (const float*)d_in[22]; const float* ln1b = (const float*)d_in[23];
    const float* w1 = (const float*)d_in[24];  const float* b1 = (const float*)d_in[25];
    const float* w2 = (const float*)d_in[26];  const float* b2 = (const float*)d_in[27];
    const float* ln2g = (const float*)d_in[28]; const float* ln2b = (const float*)d_in[29];
    const float* pw = (const float*)d_in[30];  const float* pb = (const float*)d_in[31];
    float* out = (float*)d_out;

    float *pM, *pE, *pQ, *pK, *pV, *pO, *pP, *pSb, *pSl, *pSg, *pSc, *pSs, *pT1, *pT2;
    cudaGetSymbolAddress((void**)&pM,  g_M);
    cudaGetSymbolAddress((void**)&pE,  g_E);
    cudaGetSymbolAddress((void**)&pQ,  g_Q);
    cudaGetSymbolAddress((void**)&pK,  g_K);
    cudaGetSymbolAddress((void**)&pV,  g_V);
    cudaGetSymbolAddress((void**)&pO,  g_O);
    cudaGetSymbolAddress((void**)&pP,  g_Prob);
    cudaGetSymbolAddress((void**)&pSb, g_Sbase);
    cudaGetSymbolAddress((void**)&pSl, g_Slocal);
    cudaGetSymbolAddress((void**)&pSg, g_Sglob);
    cudaGetSymbolAddress((void**)&pSc, g_Scross);
    cudaGetSymbolAddress((void**)&pSs, g_Ssum);
    cudaGetSymbolAddress((void**)&pT1, g_T1);
    cudaGetSymbolAddress((void**)&pT2, g_T2);

    cudaFuncSetAttribute(linear_tf32_kernel,
                         cudaFuncAttributeMaxDynamicSharedMemorySize, G_SMEM_BYTES);
    cudaFuncSetAttribute(attn_scores_tf32_kernel,
                         cudaFuncAttributeMaxDynamicSharedMemorySize, G_SMEM_BYTES);
    cudaFuncSetAttribute(attn_pv_tf32_kernel,
                         cudaFuncAttributeMaxDynamicSharedMemorySize, P_SMEM_BYTES);

    auto lin = [&](const float* A, const float* W, const float* bias, float* C, int Mrows,
                   const float* r1, const float* r2, int relu) {
        dim3 g(D / GBN, Mrows / GBM);
        linear_tf32_kernel<<<g, 256, G_SMEM_BYTES>>>(A, W, bias, C, Mrows, D, D, r1, r2, relu);
    };
    auto scores = [&](const float* Qp, const float* Kp2, int causal) {
        attn_scores_tf32_kernel<<<dim3(N / 128, N / 128, B * H), 256, G_SMEM_BYTES>>>(Qp, Kp2, pP, causal);
    };
    auto pv = [&](const float* Vp, int causal) {
        attn_pv_tf32_kernel<<<dim3(1, N / 128, B * H), 256, P_SMEM_BYTES>>>(pP, Vp, pO, causal);
    };

    // 1. embeddings
    embed_kernel<<<BN_ROWS, 128>>>(q, r, qry, M_emb, E_emb, Pmat);

    // 2. base MHA (Q from E, K/V from M, causal) + attn_w output
    lin(pE, biw,             bib,         pQ, BN_ROWS, nullptr, nullptr, 0);
    lin(pM, biw + D * D,     bib + D,     pK, BN_ROWS, nullptr, nullptr, 0);
    lin(pM, biw + 2 * D * D, bib + 2 * D, pV, BN_ROWS, nullptr, nullptr, 0);
    scores(pQ, pK, 1);
    softmax_kernel<<<B * H * N, 128>>>(pP, N, N, 1);
    attn_mean_kernel<<<(B * N * N) / 256, 256>>>(pP, out + BN_ROWS);
    pv(pV, 1);
    lin(pO, bow, bob, pT1, BN_ROWS, nullptr, nullptr, 0);
    ln_kernel<<<BN_ROWS, 128>>>(pT1, pM, pE, ln1g, ln1b, pSb);

    // 3. local MHA on last LW tokens (causal) -- tiny, SIMT path
    pack_loc_kernel<<<(BLW_ROWS * D) / 256, 256>>>();
    lin(pT2, liw,             lib,         pQ, BLW_ROWS, nullptr, nullptr, 0);
    lin(pT2, liw + D * D,     lib + D,     pK, BLW_ROWS, nullptr, nullptr, 0);
    lin(pT2, liw + 2 * D * D, lib + 2 * D, pV, BLW_ROWS, nullptr, nullptr, 0);
    attn_scores_kernel<<<dim3(1, 1, B * H), 256>>>(pQ, pK, pP, LW, LW, 1);
    softmax_kernel<<<B * H * LW, 128>>>(pP, LW, LW, 1);
    attn_pv_kernel<<<dim3(1, 1, B * H), 256>>>(pP, pV, pO, LW, LW, 1);
    lin(pO, low, lob, pT1, BLW_ROWS, nullptr, nullptr, 0);
    expand_local_kernel<<<(BN_ROWS * D) / 256, 256>>>(pT1);

    // 4. global MHA (self on S_base, causal)
    lin(pSb, giw,             gib,         pQ, BN_ROWS, nullptr, nullptr, 0);
    lin(pSb, giw + D * D,     gib + D,     pK, BN_ROWS, nullptr, nullptr, 0);
    lin(pSb, giw + 2 * D * D, gib + 2 * D, pV, BN_ROWS, nullptr, nullptr, 0);
    scores(pQ, pK, 1);
    softmax_kernel<<<B * H * N, 128>>>(pP, N, N, 1);
    pv(pV, 1);
    lin(pO, gow, gob, pSg, BN_ROWS, nullptr, nullptr, 0);

    // 5. cross MHA (Q from S_base, K/V from S_local, no mask)
    lin(pSb, ciw,             cib,         pQ, BN_ROWS, nullptr, nullptr, 0);
    lin(pSl, ciw + D * D,     cib + D,     pK, BN_ROWS, nullptr, nullptr, 0);
    lin(pSl, ciw + 2 * D * D, cib + 2 * D, pV, BN_ROWS, nullptr, nullptr, 0);
    scores(pQ, pK, 0);
    softmax_kernel<<<B * H * N, 128>>>(pP, N, N, 0);
    pv(pV, 0);
    lin(pO, cow, cob, pSc, BN_ROWS, nullptr, nullptr, 0);

    // 6. combine + FFN + LN2 + head
    sum4_kernel<<<(BN_ROWS * D) / 256, 256>>>();
    lin(pSs, w1, b1, pT1, BN_ROWS, nullptr, nullptr, 1);   // relu
    lin(pT1, w2, b2, pT2, BN_ROWS, nullptr, nullptr, 0);
    ln_kernel<<<BN_ROWS, 128>>>(pT2, pSs, nullptr, ln2g, ln2b, pT1);
    pred_kernel<<<BN_ROWS, 128>>>(pT1, pw, pb, out);
}

// round 5
// speedup vs baseline: 5.8910x; 1.3892x over previous
#include <cuda_runtime.h>
#include <cuda_bf16.h>
#include <math.h>
#include <stdint.h>

// ---------------------------------------------------------------------------
// Problem constants
// ---------------------------------------------------------------------------
static constexpr int B  = 16;
static constexpr int N  = 512;
static constexpr int D  = 512;
static constexpr int H  = 8;
static constexpr int HD = 64;
static constexpr int LW = 64;
static constexpr int NQ = 10000;
static constexpr int BN_ROWS  = B * N;    // 8192
static constexpr int BLW_ROWS = B * LW;   // 1024
static constexpr int DD = D * D;          // 262144 = 2^18

typedef __nv_bfloat16 bf16;
typedef __nv_bfloat162 bf162;

// ---------------------------------------------------------------------------
// Scratch (static device globals)
// ---------------------------------------------------------------------------
// f32
__device__ float g_M     [BN_ROWS * D];
__device__ float g_E     [BN_ROWS * D];
__device__ float g_T1    [BN_ROWS * D];
__device__ float g_T2    [BN_ROWS * D];
__device__ float g_Sbase [BN_ROWS * D];
__device__ float g_Slocal[BN_ROWS * D];
__device__ float g_Sglob [BN_ROWS * D];
__device__ float g_Scross[BN_ROWS * D];
__device__ float g_Ssum  [BN_ROWS * D];
__device__ float g_P32   [B * H * N * N];      // base probs (f32, for attn_w) + local scratch
// bf16
__device__ bf16 g_Mb  [BN_ROWS * D];
__device__ bf16 g_Eb  [BN_ROWS * D];
__device__ bf16 g_QK  [BN_ROWS * 1536];        // packed Q/K (and local QKV)
__device__ bf16 g_Vt  [B * H * HD * N];        // V transposed per (b,h): [e][j]
__device__ bf16 g_S16 [B * H * N * N];         // scores
__device__ bf16 g_P16 [B * H * N * N];         // probs
__device__ bf16 g_O16 [BN_ROWS * D];           // attention output (pre out-proj)
__device__ bf16 g_Sb16[BN_ROWS * D];
__device__ bf16 g_Sl16[BN_ROWS * D];
__device__ bf16 g_Ss16[BN_ROWS * D];
__device__ bf16 g_F16 [BN_ROWS * D];
__device__ bf16 g_T2b [BLW_ROWS * D];
__device__ bf16 g_Wb  [18 * DD];               // bf16 weights

// ---------------------------------------------------------------------------
// MMA helpers (bf16 m16n8k16)
// ---------------------------------------------------------------------------
__device__ __forceinline__ void cp_async16(uint32_t dst, const void* src) {
    asm volatile("cp.async.cg.shared.global [%0], [%1], 16;" :: "r"(dst), "l"(src));
}
__device__ __forceinline__ void cp_commit() {
    asm volatile("cp.async.commit_group;");
}
__device__ __forceinline__ void mma_bf16(float c[4], uint32_t a0, uint32_t a1,
                                         uint32_t a2, uint32_t a3,
                                         uint32_t b0, uint32_t b1) {
    asm volatile(
        "mma.sync.aligned.m16n8k16.row.col.f32.bf16.bf16.f32 "
        "{%0,%1,%2,%3}, {%4,%5,%6,%7}, {%8,%9}, {%0,%1,%2,%3};"
        : "+f"(c[0]), "+f"(c[1]), "+f"(c[2]), "+f"(c[3])
        : "r"(a0), "r"(a1), "r"(a2), "r"(a3), "r"(b0), "r"(b1));
}

// smem tile geometry: rows of 32 bf16 (BK) = 16 u32 + 4 pad
static constexpr int LSTR = 20;                    // u32 per row
static constexpr int L_STAGE_U32 = 256 * LSTR;     // A(128)+B(128) rows
static constexpr int PV_STAGE_U32 = 192 * LSTR;    // P(128)+Vt(64) rows

// ---------------------------------------------------------------------------
// Weight conversion: 18 slots of DD f32 -> g_Wb bf16
// slots: 0-2 base_in, 3-5 local_in, 6-8 glob_in, 9-11 cross_in,
//        12 base_out, 13 local_out, 14 glob_out, 15 cross_out, 16 w1, 17 w2
// ---------------------------------------------------------------------------
struct WSrc { const float* p[18]; };
__global__ void cvt_weights_kernel(WSrc ws) {
    for (int i = blockIdx.x * blockDim.x + threadIdx.x; i < 18 * DD;
         i += gridDim.x * blockDim.x) {
        int s = i >> 18;
        int off = i & (DD - 1);
        g_Wb[i] = __float2bfloat16(ws.p[s][off]);
    }
}

// ---------------------------------------------------------------------------
// Embedding gather: M = M_emb[q + NQ*r] + P[n],  E = E_emb[qry]  (f32 + bf16)
// ---------------------------------------------------------------------------
__global__ void embed_kernel(const int* __restrict__ q, const int* __restrict__ r,
                             const int* __restrict__ qry,
                             const float* __restrict__ M_emb,
                             const float* __restrict__ E_emb,
                             const float* __restrict__ P) {
    int row = blockIdx.x;
    int n = row & (N - 1);
    int x = q[row] + NQ * r[row];
    int e = qry[row];
    const float* msrc = M_emb + (size_t)x * D;
    const float* esrc = E_emb + (size_t)e * D;
    const float* psrc = P + (size_t)n * D;
    size_t base = (size_t)row * D;
    for (int d = threadIdx.x; d < D; d += blockDim.x) {
        float mv = msrc[d] + psrc[d];
        float ev = esrc[d];
        g_M[base + d] = mv;  g_Mb[base + d] = __float2bfloat16(mv);
        g_E[base + d] = ev;  g_Eb[base + d] = __float2bfloat16(ev);
    }
}

// ---------------------------------------------------------------------------
// BF16 tensor-core GEMM: C[m,n] = sum_k A[m,k]*W[n,k] + bias[n]
// A: [M,512] bf16 row-major (lda=512). W: [Nout,512] bf16 row-major.
// Outputs: optional f32 C32 (ld 512), optional bf16 C16 (ldc16, col offset),
// optional transposed-V write for cols >= vcol0 (into Vt[(b*H+h)*HD+e][tok]).
// 128x128 tile, BK=32, 8 warps x (64x32).
// ---------------------------------------------------------------------------
__global__ __launch_bounds__(256, 2)
void linear_bf16_kernel(const bf16* __restrict__ A, const bf16* __restrict__ W,
                        const float* __restrict__ bias,
                        float* __restrict__ C32,
                        bf16* __restrict__ C16, int ldc16, int coloff,
                        int vcol0, bf16* __restrict__ Vt,
                        int Nout, int relu) {
    __shared__ uint32_t sm[2 * L_STAGE_U32];
    const int tid  = threadIdx.x;
    const int lane = tid & 31;
    const int w    = tid >> 5;
    const int g    = lane >> 2;
    const int tg   = lane & 3;
    const int wm0  = (w >> 2) * 64;
    const int wn0  = (w & 3) * 32;
    const int m0   = blockIdx.y * 128;
    const int n0   = blockIdx.x * 128;
    const uint32_t sm_u32 = (uint32_t)__cvta_generic_to_shared(sm);

    auto load_tile = [&](int t, int s) {
        const int k0 = t * 32;
        uint32_t base = sm_u32 + (uint32_t)(s * L_STAGE_U32) * 4u;
#pragma unroll
        for (int i = 0; i < 2; i++) {
            int e = tid + i * 256;
            int row = e >> 2, ch = e & 3;
            cp_async16(base + (uint32_t)(row * LSTR + ch * 4) * 4u,
                       &A[(size_t)(m0 + row) * 512 + k0 + ch * 8]);
        }
        base += (uint32_t)(128 * LSTR) * 4u;
#pragma unroll
        for (int i = 0; i < 2; i++) {
            int e = tid + i * 256;
            int row = e >> 2, ch = e & 3;
            cp_async16(base + (uint32_t)(row * LSTR + ch * 4) * 4u,
                       &W[(size_t)(n0 + row) * 512 + k0 + ch * 8]);
        }
        cp_commit();
    };

    float acc[4][4][4] = {};
    const int NT = 16;   // 512/32
    load_tile(0, 0);
    for (int it = 0; it < NT; ++it) {
        if (it + 1 < NT) { load_tile(it + 1, (it + 1) & 1);
                           asm volatile("cp.async.wait_group 1;"); }
        else             { asm volatile("cp.async.wait_group 0;"); }
        __syncthreads();
        const uint32_t* As = sm + (it & 1) * L_STAGE_U32;
        const uint32_t* Ws = As + 128 * LSTR;
#pragma unroll
        for (int kb2 = 0; kb2 < 2; kb2++) {
            const int kc = kb2 * 8;
            uint32_t a[4][4], bq[4][2];
#pragma unroll
            for (int tm = 0; tm < 4; tm++) {
                int mr = wm0 + tm * 16 + g;
                a[tm][0] = As[mr * LSTR + kc + tg];
                a[tm][1] = As[(mr + 8) * LSTR + kc + tg];
                a[tm][2] = As[mr * LSTR + kc + 4 + tg];
                a[tm][3] = As[(mr + 8) * LSTR + kc + 4 + tg];
            }
#pragma unroll
            for (int tn = 0; tn < 4; tn++) {
                int nr = wn0 + tn * 8 + g;
                bq[tn][0] = Ws[nr * LSTR + kc + tg];
                bq[tn][1] = Ws[nr * LSTR + kc + 4 + tg];
            }
#pragma unroll
            for (int tm = 0; tm < 4; tm++)
#pragma unroll
                for (int tn = 0; tn < 4; tn++)
                    mma_bf16(acc[tm][tn], a[tm][0], a[tm][1], a[tm][2], a[tm][3],
                             bq[tn][0], bq[tn][1]);
        }
        __syncthreads();
    }

#pragma unroll
    for (int tm = 0; tm < 4; tm++) {
        int r0 = m0 + wm0 + tm * 16 + g;
        int r1 = r0 + 8;
#pragma unroll
        for (int tn = 0; tn < 4; tn++) {
            int c = n0 + wn0 + tn * 8 + tg * 2;   // global output col within Nout
            float b0 = bias[c], b1 = bias[c + 1];
            float v00 = acc[tm][tn][0] + b0;
            float v01 = acc[tm][tn][1] + b1;
            float v10 = acc[tm][tn][2] + b0;
            float v11 = acc[tm][tn][3] + b1;
            if (relu) { v00 = fmaxf(v00, 0.f); v01 = fmaxf(v01, 0.f);
                        v10 = fmaxf(v10, 0.f); v11 = fmaxf(v11, 0.f); }
            if (C32) {
                *(float2*)&C32[(size_t)r0 * 512 + c] = make_float2(v00, v01);
                *(float2*)&C32[(size_t)r1 * 512 + c] = make_float2(v10, v11);
            }
            if (C16) {
                if (c >= vcol0) {   // transposed V write
                    int ve = c - vcol0;
                    int h = ve >> 6, e0 = ve & 63;
                    int b_ = r0 >> 9;
                    int t0 = r0 & 511, t1 = r1 & 511;
                    bf16* vrow0 = Vt + ((size_t)((b_ * H + h) * HD + e0)) * N;
                    bf16* vrow1 = vrow0 + N;
                    vrow0[t0] = __float2bfloat16(v00);
                    vrow1[t0] = __float2bfloat16(v01);
                    vrow0[t1] = __float2bfloat16(v10);
                    vrow1[t1] = __float2bfloat16(v11);
                } else {
                    *(bf162*)&C16[(size_t)r0 * ldc16 + coloff + c] =
                        __floats2bfloat162_rn(v00, v01);
                    *(bf162*)&C16[(size_t)r1 * ldc16 + coloff + c] =
                        __floats2bfloat162_rn(v10, v11);
                }
            }
        }
    }
}

// ---------------------------------------------------------------------------
// BF16 attention scores: S16[z,i,j] = dot64(Q, K) * 0.125.  Q/K in g_QK
// (ld 1024, Q at col 0, K at col 512). 128x128 tile, grid (4,4,128).
// ---------------------------------------------------------------------------
__global__ __launch_bounds__(256, 2)
void scores_bf16_kernel(const bf16* __restrict__ QK, bf16* __restrict__ S16,
                        int causal) {
    const int z = blockIdx.z, b = z >> 3, h = z & 7;
    const int i0 = blockIdx.y * 128, j0 = blockIdx.x * 128;
    if (causal && j0 > i0 + 127) return;
    const bf16* Qb = QK + (size_t)(b * N) * 1024 + h * HD;
    const bf16* Kb = Qb + 512;
    bf16* Sb = S16 + (size_t)z * N * N;

    __shared__ uint32_t sm[2 * L_STAGE_U32];
    const int tid  = threadIdx.x;
    const int lane = tid & 31;
    const int w    = tid >> 5;
    const int g    = lane >> 2;
    const int tg   = lane & 3;
    const int wm0  = (w >> 2) * 64;
    const int wn0  = (w & 3) * 32;
    const uint32_t sm_u32 = (uint32_t)__cvta_generic_to_shared(sm);

    auto load_tile = [&](int t, int s) {
        const int k0 = t * 32;
        uint32_t base = sm_u32 + (uint32_t)(s * L_STAGE_U32) * 4u;
#pragma unroll
        for (int i = 0; i < 2; i++) {
            int e = tid + i * 256;
            int row = e >> 2, ch = e & 3;
            cp_async16(base + (uint32_t)(row * LSTR + ch * 4) * 4u,
                       &Qb[(size_t)(i0 + row) * 1024 + k0 + ch * 8]);
        }
        base += (uint32_t)(128 * LSTR) * 4u;
#pragma unroll
        for (int i = 0; i < 2; i++) {
            int e = tid + i * 256;
            int row = e >> 2, ch = e & 3;
            cp_async16(base + (uint32_t)(row * LSTR + ch * 4) * 4u,
                       &Kb[(size_t)(j0 + row) * 1024 + k0 + ch * 8]);
        }
        cp_commit();
    };

    float acc[4][4][4] = {};
    load_tile(0, 0);
    for (int it = 0; it < 2; ++it) {    // HD/32
        if (it == 0) { load_tile(1, 1); asm volatile("cp.async.wait_group 1;"); }
        else         { asm volatile("cp.async.wait_group 0;"); }
        __syncthreads();
        const uint32_t* As = sm + (it & 1) * L_STAGE_U32;
        const uint32_t* Ws = As + 128 * LSTR;
#pragma unroll
        for (int kb2 = 0; kb2 < 2; kb2++) {
            const int kc = kb2 * 8;
            uint32_t a[4][4], bq[4][2];
#pragma unroll
            for (int tm = 0; tm < 4; tm++) {
                int mr = wm0 + tm * 16 + g;
                a[tm][0] = As[mr * LSTR + kc + tg];
                a[tm][1] = As[(mr + 8) * LSTR + kc + tg];
                a[tm][2] = As[mr * LSTR + kc + 4 + tg];
                a[tm][3] = As[(mr + 8) * LSTR + kc + 4 + tg];
            }
#pragma unroll
            for (int tn = 0; tn < 4; tn++) {
                int nr = wn0 + tn * 8 + g;
                bq[tn][0] = Ws[nr * LSTR + kc + tg];
                bq[tn][1] = Ws[nr * LSTR + kc + 4 + tg];
            }
#pragma unroll
            for (int tm = 0; tm < 4; tm++)
#pragma unroll
                for (int tn = 0; tn < 4; tn++)
                    mma_bf16(acc[tm][tn], a[tm][0], a[tm][1], a[tm][2], a[tm][3],
                             bq[tn][0], bq[tn][1]);
        }
        __syncthreads();
    }

#pragma unroll
    for (int tm = 0; tm < 4; tm++) {
        int r0 = i0 + wm0 + tm * 16 + g;
        int r1 = r0 + 8;
#pragma unroll
        for (int tn = 0; tn < 4; tn++) {
            int c = j0 + wn0 + tn * 8 + tg * 2;
            *(bf162*)&Sb[(size_t)r0 * N + c] =
                __floats2bfloat162_rn(acc[tm][tn][0] * 0.125f, acc[tm][tn][1] * 0.125f);
            *(bf162*)&Sb[(size_t)r1 * N + c] =
                __floats2bfloat162_rn(acc[tm][tn][2] * 0.125f, acc[tm][tn][3] * 0.125f);
        }
    }
}

// ---------------------------------------------------------------------------
// BF16 PV: O16[b,i,h*64+e] = sum_j P16[z,i,j] * Vt[z,e,j]
// 128x64 tile, grid (1, 4, 128). 8 warps x (32x32).
// ---------------------------------------------------------------------------
__global__ __launch_bounds__(256, 2)
void pv_bf16_kernel(const bf16* __restrict__ P16, const bf16* __restrict__ Vt,
                    bf16* __restrict__ O16, int causal) {
    const int z = blockIdx.z, b = z >> 3, h = z & 7;
    const int i0 = blockIdx.y * 128;
    const bf16* Pb  = P16 + (size_t)z * N * N;
    const bf16* Vtz = Vt + (size_t)z * HD * N;
    bf16* Ob = O16 + (size_t)(b * N) * 512 + h * HD;

    __shared__ uint32_t sm[2 * PV_STAGE_U32];
    const int tid  = threadIdx.x;
    const int lane = tid & 31;
    const int w    = tid >> 5;
    const int g    = lane >> 2;
    const int tg   = lane & 3;
    const int wm0  = (w >> 1) * 32;
    const int wn0  = (w & 1) * 32;
    const uint32_t sm_u32 = (uint32_t)__cvta_generic_to_shared(sm);

    auto load_tile = [&](int t, int s) {
        const int k0 = t * 32;
        uint32_t base = sm_u32 + (uint32_t)(s * PV_STAGE_U32) * 4u;
#pragma unroll
        for (int i = 0; i < 2; i++) {      // P: 128 rows
            int e = tid + i * 256;
            int row = e >> 2, ch = e & 3;
            cp_async16(base + (uint32_t)(row * LSTR + ch * 4) * 4u,
                       &Pb[(size_t)(i0 + row) * N + k0 + ch * 8]);
        }
        base += (uint32_t)(128 * LSTR) * 4u;
        {                                   // Vt: 64 rows
            int row = tid >> 2, ch = tid & 3;
            cp_async16(base + (uint32_t)(row * LSTR + ch * 4) * 4u,
                       &Vtz[(size_t)row * N + k0 + ch * 8]);
        }
        cp_commit();
    };

    float acc[2][4][4] = {};
    const int kend = causal ? (i0 + 128) : N;
    const int NT = kend / 32;
    load_tile(0, 0);
    for (int it = 0; it < NT; ++it) {
        if (it + 1 < NT) { load_tile(it + 1, (it + 1) & 1);
                           asm volatile("cp.async.wait_group 1;"); }
        else             { asm volatile("cp.async.wait_group 0;"); }
        __syncthreads();
        const uint32_t* As = sm + (it & 1) * PV_STAGE_U32;
        const uint32_t* Vs = As + 128 * LSTR;
#pragma unroll
        for (int kb2 = 0; kb2 < 2; kb2++) {
            const int kc = kb2 * 8;
            uint32_t a[2][4], bq[4][2];
#pragma unroll
            for (int tm = 0; tm < 2; tm++) {
                int mr = wm0 + tm * 16 + g;
                a[tm][0] = As[mr * LSTR + kc + tg];
                a[tm][1] = As[(mr + 8) * LSTR + kc + tg];
                a[tm][2] = As[mr * LSTR + kc + 4 + tg];
                a[tm][3] = As[(mr + 8) * LSTR + kc + 4 + tg];
            }
#pragma unroll
            for (int tn = 0; tn < 4; tn++) {
                int nr = wn0 + tn * 8 + g;
                bq[tn][0] = Vs[nr * LSTR + kc + tg];
                bq[tn][1] = Vs[nr * LSTR + kc + 4 + tg];
            }
#pragma unroll
            for (int tm = 0; tm < 2; tm++)
#pragma unroll
                for (int tn = 0; tn < 4; tn++)
                    mma_bf16(acc[tm][tn], a[tm][0], a[tm][1], a[tm][2], a[tm][3],
                             bq[tn][0], bq[tn][1]);
        }
        __syncthreads();
    }

#pragma unroll
    for (int tm = 0; tm < 2; tm++) {
        int r0 = i0 + wm0 + tm * 16 + g;
        int r1 = r0 + 8;
#pragma unroll
        for (int tn = 0; tn < 4; tn++) {
            int c = wn0 + tn * 8 + tg * 2;
            *(bf162*)&Ob[(size_t)r0 * 512 + c] =
                __floats2bfloat162_rn(acc[tm][tn][0], acc[tm][tn][1]);
            *(bf162*)&Ob[(size_t)r1 * 512 + c] =
                __floats2bfloat162_rn(acc[tm][tn][2], acc[tm][tn][3]);
        }
    }
}

// ---------------------------------------------------------------------------
// Softmax over bf16 scores -> bf16 probs (+ optional f32 probs for attn_w).
// One block (128 thr) per row of 512. Zeroes causal tail.
// ---------------------------------------------------------------------------
__global__ void softmax_bf16_kernel(const bf16* __restrict__ S16,
                                    bf16* __restrict__ P16,
                                    float* __restrict__ P32, int causal) {
    int row = blockIdx.x;
    int i = row & (N - 1);
    const bf16* Sr = S16 + (size_t)row * N;
    bf16* Pr = P16 + (size_t)row * N;
    float* Pr32 = P32 ? P32 + (size_t)row * N : nullptr;
    int lim = causal ? (i + 1) : N;
    int tid = threadIdx.x;
    float v[4];
    float mx = -1e30f;
#pragma unroll
    for (int c = 0; c < 4; c++) {
        int j = tid + c * 128;
        v[c] = (j < lim) ? __bfloat162float(Sr[j]) : -1e30f;
        mx = fmaxf(mx, v[c]);
    }
    __shared__ float red[128];
    red[tid] = mx; __syncthreads();
    for (int s = 64; s > 0; s >>= 1) { if (tid < s) red[tid] = fmaxf(red[tid], red[tid + s]); __syncthreads(); }
    mx = red[0]; __syncthreads();
    float sum = 0.f;
#pragma unroll
    for (int c = 0; c < 4; c++) {
        int j = tid + c * 128;
        float e = (j < lim) ? __expf(v[c] - mx) : 0.f;
        v[c] = e; sum += e;
    }
    red[tid] = sum; __syncthreads();
    for (int s = 64; s > 0; s >>= 1) { if (tid < s) red[tid] += red[tid + s]; __syncthreads(); }
    float inv = 1.f / red[0];
#pragma unroll
    for (int c = 0; c < 4; c++) {
        int j = tid + c * 128;
        float p = v[c] * inv;
        Pr[j] = __float2bfloat16(p);
        if (Pr32) Pr32[j] = p;
    }
}

// f32 softmax (local path, Nk<=512)
__global__ void softmax_f32_kernel(float* __restrict__ S, int Nq, int Nk, int causal) {
    int row = blockIdx.x;
    int i = row % Nq;
    float* Sr = S + (size_t)row * Nk;
    int lim = causal ? (i + 1) : Nk;
    int tid = threadIdx.x;
    float v[4];
    float mx = -1e30f;
#pragma unroll
    for (int c = 0; c < 4; c++) {
        int j = tid + c * 128;
        v[c] = (j < lim) ? Sr[j] : -1e30f;
        mx = fmaxf(mx, v[c]);
    }
    __shared__ float red[128];
    red[tid] = mx; __syncthreads();
    for (int s = 64; s > 0; s >>= 1) { if (tid < s) red[tid] = fmaxf(red[tid], red[tid + s]); __syncthreads(); }
    mx = red[0]; __syncthreads();
    float sum = 0.f;
#pragma unroll
    for (int c = 0; c < 4; c++) {
        int j = tid + c * 128;
        float e = (j < lim) ? __expf(v[c] - mx) : 0.f;
        v[c] = e; sum += e;
    }
    red[tid] = sum; __syncthreads();
    for (int s = 64; s > 0; s >>= 1) { if (tid < s) red[tid] += red[tid + s]; __syncthreads(); }
    float inv = 1.f / red[0];
#pragma unroll
    for (int c = 0; c < 4; c++) {
        int j = tid + c * 128;
        if (j < Nk) Sr[j] = v[c] * inv;
    }
}

// ---------------------------------------------------------------------------
// attn_w output: mean over heads of base probs (f32) -> d_out + B*N
// ---------------------------------------------------------------------------
__global__ void attn_mean_kernel(const float* __restrict__ Pm, float* __restrict__ out) {
    size_t idx = (size_t)blockIdx.x * blockDim.x + threadIdx.x;
    if (idx >= (size_t)B * N * N) return;
    size_t j = idx % N;
    size_t i = (idx / N) % N;
    size_t b = idx / ((size_t)N * N);
    float s = 0.f;
#pragma unroll
    for (int h = 0; h < H; h++)
        s += Pm[(((b * H + h) * N + i) * N) + j];
    out[idx] = s * (1.f / H);
}

// ---------------------------------------------------------------------------
// SIMT local attention (LW=64): scores, PV (bf16 inputs from g_QK ld 1536)
// ---------------------------------------------------------------------------
__global__ void local_scores_kernel(const bf16* __restrict__ QK, float* __restrict__ S) {
    int z = blockIdx.z, b = z >> 3, h = z & 7;
    const bf16* Qb = QK + (size_t)(b * LW) * 1536 + h * HD;
    const bf16* Kb = Qb + 512;
    float* Sb = S + (size_t)z * LW * LW;
    __shared__ float Qs[16][64];
    __shared__ float Ks[16][64];
    int tid = threadIdx.x, tx = tid & 15, ty = tid >> 4;
    float acc[4][4] = {};
    for (int k0 = 0; k0 < HD; k0 += 16) {
        for (int idx = tid; idx < 64 * 16; idx += 256) {
            int i = idx >> 4, j = idx & 15;
            Qs[j][i] = __bfloat162float(Qb[(size_t)i * 1536 + k0 + j]);
            Ks[j][i] = __bfloat162float(Kb[(size_t)i * 1536 + k0 + j]);
        }
        __syncthreads();
#pragma unroll
        for (int k = 0; k < 16; k++) {
            float a[4], wv[4];
#pragma unroll
            for (int i = 0; i < 4; i++) a[i] = Qs[k][ty * 4 + i];
#pragma unroll
            for (int j = 0; j < 4; j++) wv[j] = Ks[k][tx * 4 + j];
#pragma unroll
            for (int i = 0; i < 4; i++)
#pragma unroll
                for (int j = 0; j < 4; j++) acc[i][j] += a[i] * wv[j];
        }
        __syncthreads();
    }
#pragma unroll
    for (int i = 0; i < 4; i++)
#pragma unroll
        for (int j = 0; j < 4; j++)
            Sb[(size_t)(ty * 4 + i) * LW + tx * 4 + j] = acc[i][j] * 0.125f;
}

__global__ void local_pv_kernel(const float* __restrict__ Pm, const bf16* __restrict__ QK,
                                bf16* __restrict__ O16) {
    int z = blockIdx.z, b = z >> 3, h = z & 7;
    const float* Pb = Pm + (size_t)z * LW * LW;
    const bf16* Vb = QK + (size_t)(b * LW) * 1536 + 1024 + h * HD;
    bf16* Ob = O16 + (size_t)(b * LW) * 512 + h * HD;
    __shared__ float Ps[64][17];
    __shared__ float Vs[16][64];
    int tid = threadIdx.x, tx = tid & 15, ty = tid >> 4;
    float acc[4][4] = {};
    for (int k0 = 0; k0 < LW; k0 += 16) {
        for (int idx = tid; idx < 64 * 16; idx += 256) {
            int i = idx >> 4, j = idx & 15;
            Ps[i][j] = Pb[(size_t)i * LW + k0 + j];
        }
        for (int idx = tid; idx < 16 * 64; idx += 256) {
            int k = idx >> 6, e = idx & 63;
            Vs[k][e] = __bfloat162float(Vb[(size_t)(k0 + k) * 1536 + e]);
        }
        __syncthreads();
#pragma unroll
        for (int k = 0; k < 16; k++) {
            float a[4], wv[4];
#pragma unroll
            for (int i = 0; i < 4; i++) a[i] = Ps[ty * 4 + i][k];
#pragma unroll
            for (int j = 0; j < 4; j++) wv[j] = Vs[k][tx * 4 + j];
#pragma unroll
            for (int i = 0; i < 4; i++)
#pragma unroll
                for (int j = 0; j < 4; j++) acc[i][j] += a[i] * wv[j];
        }
        __syncthreads();
    }
#pragma unroll
    for (int i = 0; i < 4; i++)
#pragma unroll
        for (int j = 0; j < 4; j++)
            Ob[(size_t)(ty * 4 + i) * 512 + tx * 4 + j] = __float2bfloat16(acc[i][j]);
}

// ---------------------------------------------------------------------------
// LayerNorm: out = LN(X + r1? + r2?) * g + b   (f32 out + optional bf16 out)
// ---------------------------------------------------------------------------
__global__ void ln_kernel(const float* __restrict__ X, const float* __restrict__ r1,
                          const float* __restrict__ r2, const float* __restrict__ g,
                          const float* __restrict__ bvec, float* __restrict__ out,
                          bf16* __restrict__ out16) {
    int row = blockIdx.x;
    size_t base = (size_t)row * D;
    int tid = threadIdx.x;
    float v[4];
    float s = 0.f;
#pragma unroll
    for (int c = 0; c < 4; c++) {
        int d = tid + c * 128;
        float t = X[base + d];
        if (r1) t += r1[base + d];
        if (r2) t += r2[base + d];
        v[c] = t; s += t;
    }
    __shared__ float red[128];
    red[tid] = s; __syncthreads();
    for (int st = 64; st > 0; st >>= 1) { if (tid < st) red[tid] += red[tid + st]; __syncthreads(); }
    float mean = red[0] * (1.f / D);
    __syncthreads();
    float vs = 0.f;
#pragma unroll
    for (int c = 0; c < 4; c++) { float dl = v[c] - mean; vs += dl * dl; }
    red[tid] = vs; __syncthreads();
    for (int st = 64; st > 0; st >>= 1) { if (tid < st) red[tid] += red[tid + st]; __syncthreads(); }
    float inv = rsqrtf(red[0] * (1.f / D) + 1e-5f);
#pragma unroll
    for (int c = 0; c < 4; c++) {
        int d = tid + c * 128;
        float o = (v[c] - mean) * inv * g[d] + bvec[d];
        out[base + d] = o;
        if (out16) out16[base + d] = __float2bfloat16(o);
    }
}

// ---------------------------------------------------------------------------
// Misc elementwise kernels
// ---------------------------------------------------------------------------
__global__ void pack_loc_kernel() {          // Sb16 last LW rows/b -> T2b
    int idx = blockIdx.x * blockDim.x + threadIdx.x;   // over 1024*512
    int d = idx & (D - 1);
    int row = idx >> 9;
    int b = row >> 6;
    int i = row & (LW - 1);
    g_T2b[idx] = g_Sb16[((size_t)(b * N + (N - LW) + i) << 9) + d];
}

__global__ void expand_local_kernel(const float* __restrict__ packed) {
    size_t idx = (size_t)blockIdx.x * blockDim.x + threadIdx.x;  // over B*N*D
    int d = (int)(idx & (D - 1));
    int row = (int)(idx >> 9);
    int b = row >> 9;
    int n = row & (N - 1);
    float v = 0.f;
    if (n >= N - LW)
        v = packed[(((size_t)b * LW + (n - (N - LW))) << 9) + d];
    g_Slocal[idx] = v;
    g_Sl16[idx] = __float2bfloat16(v);
}

__global__ void sum4_kernel() {
    size_t idx = (size_t)blockIdx.x * blockDim.x + threadIdx.x;
    float v = g_Sbase[idx] + g_Slocal[idx] + g_Sglob[idx] + g_Scross[idx];
    g_Ssum[idx] = v;
    g_Ss16[idx] = __float2bfloat16(v);
}

__global__ void pred_kernel(const float* __restrict__ F, const float* __restrict__ pw,
                            const float* __restrict__ pb, float* __restrict__ out) {
    int row = blockIdx.x;
    int tid = threadIdx.x;
    const float* x = F + (size_t)row * D;
    float s = 0.f;
    for (int d = tid; d < D; d += 128) s += x[d] * pw[d];
    __shared__ float red[128];
    red[tid] = s; __syncthreads();
    for (int st = 64; st > 0; st >>= 1) { if (tid < st) red[tid] += red[tid + st]; __syncthreads(); }
    if (tid == 0) out[row] = 1.f / (1.f + __expf(-(red[0] + pb[0])));
}

// ---------------------------------------------------------------------------
// Launch
// ---------------------------------------------------------------------------
extern "C" void kernel_launch(void* const* d_in, const int* in_sizes, int n_in,
                              void* d_out, int out_size) {
    (void)in_sizes; (void)n_in; (void)out_size;
    const int*   q     = (const int*)d_in[0];
    const int*   r     = (const int*)d_in[1];
    const int*   qry   = (const int*)d_in[2];
    const float* M_emb = (const float*)d_in[3];
    const float* E_emb = (const float*)d_in[4];
    const float* Pmat  = (const float*)d_in[5];
    const float* biw = (const float*)d_in[6];  const float* bib = (const float*)d_in[7];
    const float* bow = (const float*)d_in[8];  const float* bob = (const float*)d_in[9];
    const float* liw = (const float*)d_in[10]; const float* lib = (const float*)d_in[11];
    const float* low = (const float*)d_in[12]; const float* lob = (const float*)d_in[13];
    const float* giw = (const float*)d_in[14]; const float* gib = (const float*)d_in[15];
    const float* gow = (const float*)d_in[16]; const float* gob = (const float*)d_in[17];
    const float* ciw = (const float*)d_in[18]; const float* cib = (const float*)d_in[19];
    const float* cow = (const float*)d_in[20]; const float* cob = (const float*)d_in[21];
    const float* ln1g = (const float*)d_in[22]; const float* ln1b = (const float*)d_in[23];
    const float* w1 = (const float*)d_in[24];  const float* b1 = (const float*)d_in[25];
    const float* w2 = (const float*)d_in[26];  const float* b2 = (const float*)d_in[27];
    const float* ln2g = (const float*)d_in[28]; const float* ln2b = (const float*)d_in[29];
    const float* pw = (const float*)d_in[30];  const float* pb = (const float*)d_in[31];
    float* out = (float*)d_out;

    float *pM, *pE, *pT1, *pT2, *pSb, *pSl, *pSg, *pSc, *pSs, *pP32;
    bf16 *pMb, *pEb, *pQK, *pVt, *pS16, *pP16, *pO16, *pSb16, *pSl16, *pSs16, *pF16, *pT2b, *pWb;
    cudaGetSymbolAddress((void**)&pM,   g_M);
    cudaGetSymbolAddress((void**)&pE,   g_E);
    cudaGetSymbolAddress((void**)&pT1,  g_T1);
    cudaGetSymbolAddress((void**)&pT2,  g_T2);
    cudaGetSymbolAddress((void**)&pSb,  g_Sbase);
    cudaGetSymbolAddress((void**)&pSl,  g_Slocal);
    cudaGetSymbolAddress((void**)&pSg,  g_Sglob);
    cudaGetSymbolAddress((void**)&pSc,  g_Scross);
    cudaGetSymbolAddress((void**)&pSs,  g_Ssum);
    cudaGetSymbolAddress((void**)&pP32, g_P32);
    cudaGetSymbolAddress((void**)&pMb,  g_Mb);
    cudaGetSymbolAddress((void**)&pEb,  g_Eb);
    cudaGetSymbolAddress((void**)&pQK,  g_QK);
    cudaGetSymbolAddress((void**)&pVt,  g_Vt);
    cudaGetSymbolAddress((void**)&pS16, g_S16);
    cudaGetSymbolAddress((void**)&pP16, g_P16);
    cudaGetSymbolAddress((void**)&pO16, g_O16);
    cudaGetSymbolAddress((void**)&pSb16, g_Sb16);
    cudaGetSymbolAddress((void**)&pSl16, g_Sl16);
    cudaGetSymbolAddress((void**)&pSs16, g_Ss16);
    cudaGetSymbolAddress((void**)&pF16, g_F16);
    cudaGetSymbolAddress((void**)&pT2b, g_T2b);
    cudaGetSymbolAddress((void**)&pWb,  g_Wb);

    // weight slots in g_Wb (bf16): see cvt_weights_kernel
    WSrc ws;
    ws.p[0] = biw; ws.p[1] = biw + DD; ws.p[2] = biw + 2 * DD;
    ws.p[3] = liw; ws.p[4] = liw + DD; ws.p[5] = liw + 2 * DD;
    ws.p[6] = giw; ws.p[7] = giw + DD; ws.p[8] = giw + 2 * DD;
    ws.p[9] = ciw; ws.p[10] = ciw + DD; ws.p[11] = ciw + 2 * DD;
    ws.p[12] = bow; ws.p[13] = low; ws.p[14] = gow; ws.p[15] = cow;
    ws.p[16] = w1; ws.p[17] = w2;
    cvt_weights_kernel<<<4608, 256>>>(ws);

    const int BIG = 1 << 30;
    auto lin = [&](const bf16* A, const bf16* W, const float* bias,
                   float* C32, bf16* C16, int ldc16, int coloff, int vcol0,
                   int Mrows, int Nout, int relu) {
        dim3 g(Nout / 128, Mrows / 128);
        linear_bf16_kernel<<<g, 256>>>(A, W, bias, C32, C16, ldc16, coloff,
                                       vcol0, pVt, Nout, relu);
    };

    // 1. embeddings
    embed_kernel<<<BN_ROWS, 128>>>(q, r, qry, M_emb, E_emb, Pmat);

    // 2. base MHA (Q from E, K/V from M, causal) + attn_w output
    lin(pEb, pWb + 0 * DD, bib,          nullptr, pQK, 1024, 0,   BIG, BN_ROWS, 512, 0);   // Q
    lin(pMb, pWb + 1 * DD, bib + D,      nullptr, pQK, 1024, 512, 512, BN_ROWS, 1024, 0);  // K + Vt
    scores_bf16_kernel<<<dim3(4, 4, 128), 256>>>(pQK, pS16, 1);
    softmax_bf16_kernel<<<B * H * N, 128>>>(pS16, pP16, pP32, 1);
    attn_mean_kernel<<<(B * N * N) / 256, 256>>>(pP32, out + BN_ROWS);
    pv_bf16_kernel<<<dim3(1, 4, 128), 256>>>(pP16, pVt, pO16, 1);
    lin(pO16, pWb + 12 * DD, bob, pT1, nullptr, 0, 0, BIG, BN_ROWS, 512, 0);
    ln_kernel<<<BN_ROWS, 128>>>(pT1, pM, pE, ln1g, ln1b, pSb, pSb16);

    // 3. local MHA on last LW tokens (causal) -- SIMT path
    pack_loc_kernel<<<(BLW_ROWS * D) / 256, 256>>>();
    lin(pT2b, pWb + 3 * DD, lib, nullptr, pQK, 1536, 0, BIG, BLW_ROWS, 1536, 0);  // fused QKV
    local_scores_kernel<<<dim3(1, 1, 128), 256>>>(pQK, pP32);
    softmax_f32_kernel<<<B * H * LW, 128>>>(pP32, LW, LW, 1);
    local_pv_kernel<<<dim3(1, 1, 128), 256>>>(pP32, pQK, pO16);
    lin(pO16, pWb + 13 * DD, lob, pT1, nullptr, 0, 0, BIG, BLW_ROWS, 512, 0);
    expand_local_kernel<<<(BN_ROWS * D) / 256, 256>>>(pT1);

    // 4. global MHA (self on S_base, causal) -- fused QKV
    lin(pSb16, pWb + 6 * DD, gib, nullptr, pQK, 1024, 0, 1024, BN_ROWS, 1536, 0);
    scores_bf16_kernel<<<dim3(4, 4, 128), 256>>>(pQK, pS16, 1);
    softmax_bf16_kernel<<<B * H * N, 128>>>(pS16, pP16, nullptr, 1);
    pv_bf16_kernel<<<dim3(1, 4, 128), 256>>>(pP16, pVt, pO16, 1);
    lin(pO16, pWb + 14 * DD, gob, pSg, nullptr, 0, 0, BIG, BN_ROWS, 512, 0);

    // 5. cross MHA (Q from S_base, K/V from S_local, no mask)
    lin(pSb16, pWb + 9 * DD,  cib,     nullptr, pQK, 1024, 0,   BIG, BN_ROWS, 512, 0);
    lin(pSl16, pWb + 10 * DD, cib + D, nullptr, pQK, 1024, 512, 512, BN_ROWS, 1024, 0);
    scores_bf16_kernel<<<dim3(4, 4, 128), 256>>>(pQK, pS16, 0);
    softmax_bf16_kernel<<<B * H * N, 128>>>(pS16, pP16, nullptr, 0);
    pv_bf16_kernel<<<dim3(1, 4, 128), 256>>>(pP16, pVt, pO16, 0);
    lin(pO16, pWb + 15 * DD, cob, pSc, nullptr, 0, 0, BIG, BN_ROWS, 512, 0);

    // 6. combine + FFN + LN2 + head
    sum4_kernel<<<(BN_ROWS * D) / 256, 256>>>();
    lin(pSs16, pWb + 16 * DD, b1, nullptr, pF16, 512, 0, BIG, BN_ROWS, 512, 1);  // relu
    lin(pF16,  pWb + 17 * DD, b2, pT2, nullptr, 0, 0, BIG, BN_ROWS, 512, 0);
    ln_kernel<<<BN_ROWS, 128>>>(pT2, pSs, nullptr, ln2g, ln2b, pT1, nullptr);
    pred_kernel<<<BN_ROWS, 128>>>(pT1, pw, pb, out);
}